// round 11
// baseline (speedup 1.0000x reference)
#include <cuda_runtime.h>
#include <cuda_fp16.h>
#include <math.h>

// Problem constants (fixed by the dataset)
#define N_NODES 100000
#define N_TOT   200000            // both towers fused
#define N_EDGES 1600000
#define E_TOT   3200000
#define G_GRAPHS 64
#define HID 128
#define OUT_DIM 64

#define SCAN_BLK 1024
#define N_SCAN_BLOCKS ((N_TOT + SCAN_BLK - 1) / SCAN_BLK)   // 196

// ---------------------------------------------------------------------------
// Scratch (device globals; allocation-free per harness rules)
// ---------------------------------------------------------------------------
__device__ __half g_bufAh[N_TOT * HID];     // node features (fp16), both towers
__device__ __half g_bufBh[N_TOT * HID];     // xw = x @ W (fp16)
__device__ float g_deg[N_TOT];
__device__ float g_dinv[N_TOT];
__device__ int   g_count[N_TOT];            // counts, then cursor
__device__ int   g_off[N_TOT + 1];          // CSR offsets (by global dst)
__device__ int   g_blocksum[N_SCAN_BLOCKS];
__device__ int2  g_edge[E_TOT];             // {src, nrm-as-float-bits} per sorted edge
__device__ float g_pooled[2 * G_GRAPHS * HID];
__device__ float g_cnt[2 * G_GRAPHS];
__device__ float g_h[2][G_GRAPHS * OUT_DIM];

// ---------------------------------------------------------------------------
// fp32 -> fp16 conversion of input features (both towers)
// ---------------------------------------------------------------------------
__global__ void conv_x_kernel(const float* __restrict__ x1,
                              const float* __restrict__ x2) {
    int i = blockIdx.x * blockDim.x + threadIdx.x;   // per 4 elements
    if (i < N_TOT * 32) {
        const float* x = (i < N_NODES * 32) ? x1 : x2;
        int li = (i < N_NODES * 32) ? i : (i - N_NODES * 32);
        float4 v = ((const float4*)x)[li];
        uint2 o;
        *(__half2*)&o.x = __floats2half2_rn(v.x, v.y);
        *(__half2*)&o.y = __floats2half2_rn(v.z, v.w);
        ((uint2*)g_bufAh)[i] = o;
    }
}

// ---------------------------------------------------------------------------
// Degree + counts (both edge lists, global node ids)
// ---------------------------------------------------------------------------
__global__ void zero_deg_kernel() {
    int i = blockIdx.x * blockDim.x + threadIdx.x;
    if (i < N_TOT) { g_deg[i] = 0.0f; g_count[i] = 0; }
}

__global__ void deg_count_kernel(const int* __restrict__ ei1,
                                 const float* __restrict__ ea1,
                                 const int* __restrict__ ei2,
                                 const float* __restrict__ ea2) {
    int e = blockIdx.x * blockDim.x + threadIdx.x;
    if (e < E_TOT) {
        int tower = (e >= N_EDGES) ? 1 : 0;
        int le = e - tower * N_EDGES;
        const int* ei = tower ? ei2 : ei1;
        const float* ea = tower ? ea2 : ea1;
        int di = ei[N_EDGES + le] + tower * N_NODES;
        atomicAdd(&g_deg[di], ea[le]);
        atomicAdd(&g_count[di], 1);
    }
}

// ---------------------------------------------------------------------------
// Exclusive scan of g_count -> g_off
// ---------------------------------------------------------------------------
__global__ void __launch_bounds__(SCAN_BLK)
scan_block_kernel() {
    __shared__ int s[SCAN_BLK];
    int i = blockIdx.x * SCAN_BLK + threadIdx.x;
    int v = (i < N_TOT) ? g_count[i] : 0;
    s[threadIdx.x] = v;
    __syncthreads();
    #pragma unroll
    for (int d = 1; d < SCAN_BLK; d <<= 1) {
        int t = (threadIdx.x >= d) ? s[threadIdx.x - d] : 0;
        __syncthreads();
        s[threadIdx.x] += t;
        __syncthreads();
    }
    if (i < N_TOT) g_off[i] = s[threadIdx.x] - v;
    if (threadIdx.x == SCAN_BLK - 1) g_blocksum[blockIdx.x] = s[threadIdx.x];
}

// Parallel top-level scan over 196 block sums (one block, 256 threads)
__global__ void scan_top_kernel() {
    __shared__ int s[256];
    int t = threadIdx.x;
    int v = (t < N_SCAN_BLOCKS) ? g_blocksum[t] : 0;
    s[t] = v;
    __syncthreads();
    #pragma unroll
    for (int d = 1; d < 256; d <<= 1) {
        int tv = (t >= d) ? s[t - d] : 0;
        __syncthreads();
        s[t] += tv;
        __syncthreads();
    }
    if (t < N_SCAN_BLOCKS) g_blocksum[t] = s[t] - v;   // exclusive
    if (t == 255) g_off[N_TOT] = s[255];
}

// also computes dinv (deg is final by now)
__global__ void scan_add_kernel() {
    int i = blockIdx.x * blockDim.x + threadIdx.x;
    if (i < N_TOT) {
        int o = g_off[i] + g_blocksum[i >> 10];
        g_off[i] = o;
        g_count[i] = o;
        g_dinv[i] = rsqrtf(g_deg[i] + 1.0f);
    }
}

__global__ void scatter_kernel(const int* __restrict__ ei1,
                               const float* __restrict__ ea1,
                               const int* __restrict__ ei2,
                               const float* __restrict__ ea2) {
    int e = blockIdx.x * blockDim.x + threadIdx.x;
    if (e < E_TOT) {
        int tower = (e >= N_EDGES) ? 1 : 0;
        int le = e - tower * N_EDGES;
        const int* ei = tower ? ei2 : ei1;
        const float* ea = tower ? ea2 : ea1;
        int si = ei[le] + tower * N_NODES;
        int di = ei[N_EDGES + le] + tower * N_NODES;
        int pos = atomicAdd(&g_count[di], 1);
        float nrm = g_dinv[si] * ea[le] * g_dinv[di];
        g_edge[pos] = make_int2(si, __float_as_int(nrm));
    }
}

// ---------------------------------------------------------------------------
// GEMM (HFMA2, pre-splatted X): bufB[n,c] = sum_k bufA[n,k] * W[k,c]
// Block tile 128(M) x 64(N); grid = (row blocks, 2 col halves).
// fp16 accumulate over chunks of 8 k, promoted to fp32.  (At HFMA2 issue floor.)
// ---------------------------------------------------------------------------
#define WSTR2 32
#define GEMM_SMEM_BYTES (HID * 128 * 4 + HID * WSTR2 * 4)   // 64KB + 16KB

__global__ void __launch_bounds__(256, 2)
gemm_kernel(const float* __restrict__ W)
{
    extern __shared__ __half2 smem2[];
    __half2* sXd = smem2;               // [k*128 + r], splatted
    __half2* sW2 = smem2 + HID * 128;   // [k*WSTR2 + cp]

    const int tid  = threadIdx.x;
    const int row0 = blockIdx.x * 128;
    const int gy   = blockIdx.y;        // column half

    // Load W slice (128 k x 64 cols), fp32 -> half2 col-pairs
    {
        const float4* W4 = (const float4*)W;
        #pragma unroll
        for (int i = 0; i < 8; ++i) {
            int idx = tid + i * 256;     // 0..2047
            int k  = idx >> 4;
            int c4 = idx & 15;
            float4 v = W4[k * 32 + gy * 16 + c4];
            uint2 o;
            *(__half2*)&o.x = __floats2half2_rn(v.x, v.y);
            *(__half2*)&o.y = __floats2half2_rn(v.z, v.w);
            *(uint2*)&sW2[k * WSTR2 + c4 * 2] = o;
        }
    }

    // Load X tile (128 rows x 128 k fp16), splat each value into sXd[k][r]
    {
        const uint4* Xg = (const uint4*)g_bufAh;   // 8 halfs per uint4
        #pragma unroll
        for (int i = 0; i < 8; ++i) {
            int idx = tid + i * 256;      // 0..2047
            int r   = idx & 127;
            int k8  = idx >> 7;           // 0..15, chunk of 8 k
            int grow = row0 + r;
            uint4 u = make_uint4(0u, 0u, 0u, 0u);
            if (grow < N_TOT) u = Xg[(size_t)grow * 16 + k8];
            const __half* ph = (const __half*)&u;
            #pragma unroll
            for (int t = 0; t < 8; ++t)
                sXd[(k8 * 8 + t) * 128 + r] = __half2half2(ph[t]);
        }
    }
    __syncthreads();

    const int tx = tid & 15;   // cols tx*4 .. tx*4+3 within the 64-col slice
    const int ty = tid >> 4;   // rows ty*4 and 64+ty*4

    float accf[8][4];
    #pragma unroll
    for (int i = 0; i < 8; ++i)
        #pragma unroll
        for (int j = 0; j < 4; ++j) accf[i][j] = 0.0f;

    #pragma unroll
    for (int kc = 0; kc < 16; ++kc) {        // 16 chunks of 8 k
        __half2 acc2[8][2];
        #pragma unroll
        for (int i = 0; i < 8; ++i) {
            acc2[i][0] = __floats2half2_rn(0.0f, 0.0f);
            acc2[i][1] = __floats2half2_rn(0.0f, 0.0f);
        }

        #pragma unroll
        for (int kk = 0; kk < 8; ++kk) {
            int k = kc * 8 + kk;
            uint4 xva = *(const uint4*)&sXd[k * 128 + ty * 4];
            uint4 xvb = *(const uint4*)&sXd[k * 128 + 64 + ty * 4];
            const __half2* pa = (const __half2*)&xva;
            const __half2* pb = (const __half2*)&xvb;

            __half2 wr0 = sW2[k * WSTR2 + tx * 2];
            __half2 wr1 = sW2[k * WSTR2 + tx * 2 + 1];

            #pragma unroll
            for (int i = 0; i < 4; ++i) {
                acc2[i][0] = __hfma2(pa[i], wr0, acc2[i][0]);
                acc2[i][1] = __hfma2(pa[i], wr1, acc2[i][1]);
                acc2[i + 4][0] = __hfma2(pb[i], wr0, acc2[i + 4][0]);
                acc2[i + 4][1] = __hfma2(pb[i], wr1, acc2[i + 4][1]);
            }
        }

        #pragma unroll
        for (int i = 0; i < 8; ++i) {
            float2 f0 = __half22float2(acc2[i][0]);
            float2 f1 = __half22float2(acc2[i][1]);
            accf[i][0] += f0.x; accf[i][1] += f0.y;
            accf[i][2] += f1.x; accf[i][3] += f1.y;
        }
    }

    // Epilogue: fp32 acc -> fp16 global
    const int col0 = gy * 64 + tx * 4;
    #pragma unroll
    for (int i = 0; i < 8; ++i) {
        int r = (i < 4) ? (ty * 4 + i) : (64 + ty * 4 + i - 4);
        int grow = row0 + r;
        if (grow < N_TOT) {
            uint2 o;
            *(__half2*)&o.x = __floats2half2_rn(accf[i][0], accf[i][1]);
            *(__half2*)&o.y = __floats2half2_rn(accf[i][2], accf[i][3]);
            *(uint2*)&g_bufBh[(size_t)grow * HID + col0] = o;
        }
    }
}

// ---------------------------------------------------------------------------
// Aggregation: HALF-WARP per destination node (16 lanes x 8 channels).
// Packed edge records, 4-edge unroll for memory-level parallelism.
// out = act( bias + dinv*dinv * xw[self] + sum_j nrm[j] * xw[src[j]] )
// ---------------------------------------------------------------------------
__device__ __forceinline__ void fma8(float* a, const uint4& v, float n) {
    const __half2* p = (const __half2*)&v;
    float2 q0 = __half22float2(p[0]);
    float2 q1 = __half22float2(p[1]);
    float2 q2 = __half22float2(p[2]);
    float2 q3 = __half22float2(p[3]);
    a[0] += n * q0.x; a[1] += n * q0.y;
    a[2] += n * q1.x; a[3] += n * q1.y;
    a[4] += n * q2.x; a[5] += n * q2.y;
    a[6] += n * q3.x; a[7] += n * q3.y;
}

__global__ void __launch_bounds__(256)
agg_kernel(const float* __restrict__ bias, int act)
{
    int node = (blockIdx.x * blockDim.x + threadIdx.x) >> 4;  // half-warp id
    int ln   = threadIdx.x & 15;
    if (node >= N_TOT) return;

    const uint4* xw = (const uint4*)g_bufBh;

    int beg = g_off[node];
    int end = g_off[node + 1];

    float s = g_dinv[node];
    s = s * s;
    float4 b0 = ((const float4*)bias)[ln * 2];
    float4 b1 = ((const float4*)bias)[ln * 2 + 1];
    float a[8] = { b0.x, b0.y, b0.z, b0.w, b1.x, b1.y, b1.z, b1.w };

    uint4 self = xw[(size_t)node * 16 + ln];
    fma8(a, self, s);

    int j = beg;
    for (; j + 3 < end; j += 4) {
        int2 e0 = g_edge[j];
        int2 e1 = g_edge[j + 1];
        int2 e2 = g_edge[j + 2];
        int2 e3 = g_edge[j + 3];
        uint4 v0 = xw[(size_t)e0.x * 16 + ln];
        uint4 v1 = xw[(size_t)e1.x * 16 + ln];
        uint4 v2 = xw[(size_t)e2.x * 16 + ln];
        uint4 v3 = xw[(size_t)e3.x * 16 + ln];
        fma8(a, v0, __int_as_float(e0.y));
        fma8(a, v1, __int_as_float(e1.y));
        fma8(a, v2, __int_as_float(e2.y));
        fma8(a, v3, __int_as_float(e3.y));
    }
    for (; j < end; ++j) {
        int2 e0 = g_edge[j];
        uint4 v0 = xw[(size_t)e0.x * 16 + ln];
        fma8(a, v0, __int_as_float(e0.y));
    }

    if (act) {
        #pragma unroll
        for (int i = 0; i < 8; ++i) a[i] = tanhf(a[i]);
    }
    uint4 o;
    *(__half2*)&o.x = __floats2half2_rn(a[0], a[1]);
    *(__half2*)&o.y = __floats2half2_rn(a[2], a[3]);
    *(__half2*)&o.z = __floats2half2_rn(a[4], a[5]);
    *(__half2*)&o.w = __floats2half2_rn(a[6], a[7]);
    ((uint4*)g_bufAh)[(size_t)node * 16 + ln] = o;
}

// ---------------------------------------------------------------------------
// Global mean pool (batch sorted per tower). grid = 2 * POOL_BLOCKS_T.
// ---------------------------------------------------------------------------
#define POOL_CHUNK 128
#define POOL_BLOCKS_T ((N_NODES + POOL_CHUNK - 1) / POOL_CHUNK)

__global__ void pool_zero_kernel() {
    int i = blockIdx.x * blockDim.x + threadIdx.x;
    if (i < 2 * G_GRAPHS * HID) g_pooled[i] = 0.0f;
    if (i < 2 * G_GRAPHS) g_cnt[i] = 0.0f;
}

__global__ void pool_kernel(const int* __restrict__ batch1,
                            const int* __restrict__ batch2) {
    int tower = (blockIdx.x >= POOL_BLOCKS_T) ? 1 : 0;
    const int* batch = tower ? batch2 : batch1;
    int blk = blockIdx.x - tower * POOL_BLOCKS_T;
    int c  = threadIdx.x;
    int n0 = blk * POOL_CHUNK;
    int n1 = n0 + POOL_CHUNK;
    if (n1 > N_NODES) n1 = N_NODES;
    if (n0 >= N_NODES) return;

    int gbase = tower * G_GRAPHS;
    size_t nodeoff = (size_t)tower * N_NODES;

    float acc = 0.0f;
    int cur = batch[n0];
    int run = 0;
    for (int n = n0; n < n1; ++n) {
        int g = batch[n];
        if (g != cur) {
            atomicAdd(&g_pooled[(gbase + cur) * HID + c], acc);
            if (c == 0) atomicAdd(&g_cnt[gbase + cur], (float)run);
            acc = 0.0f; run = 0; cur = g;
        }
        acc += __half2float(g_bufAh[(nodeoff + n) * HID + c]);
        run++;
    }
    atomicAdd(&g_pooled[(gbase + cur) * HID + c], acc);
    if (c == 0) atomicAdd(&g_cnt[gbase + cur], (float)run);
}

// ---------------------------------------------------------------------------
// MLP head: fc1 (128->64, relu) + 5 x fc (64->64, relu). grid = 2 (towers).
// ---------------------------------------------------------------------------
__global__ void __launch_bounds__(512)
mlp_kernel(const float* __restrict__ fcW1, const float* __restrict__ fcb1,
           const float* __restrict__ fcW,  const float* __restrict__ fcb)
{
    __shared__ float ha[G_GRAPHS * OUT_DIM];
    __shared__ float hb[G_GRAPHS * OUT_DIM];
    int t = threadIdx.x;
    int tower = blockIdx.x;
    int gbase = tower * G_GRAPHS;

    for (int idx = t; idx < G_GRAPHS * OUT_DIM; idx += 512) {
        int g = idx >> 6, o = idx & 63;
        float ic = g_cnt[gbase + g];
        ic = 1.0f / fmaxf(ic, 1.0f);
        float s = fcb1[o];
        #pragma unroll 4
        for (int k = 0; k < HID; ++k)
            s += g_pooled[(gbase + g) * HID + k] * ic * fcW1[k * OUT_DIM + o];
        ha[idx] = fmaxf(s, 0.0f);
    }
    __syncthreads();

    float* srcb = ha;
    float* dstb = hb;
    for (int L = 0; L < 5; ++L) {
        const float* Wp = fcW + L * OUT_DIM * OUT_DIM;
        const float* bp = fcb + L * OUT_DIM;
        for (int idx = t; idx < G_GRAPHS * OUT_DIM; idx += 512) {
            int g = idx >> 6, o = idx & 63;
            float s = bp[o];
            #pragma unroll 8
            for (int k = 0; k < OUT_DIM; ++k)
                s += srcb[g * OUT_DIM + k] * Wp[k * OUT_DIM + o];
            dstb[idx] = fmaxf(s, 0.0f);
        }
        __syncthreads();
        float* tmp = srcb; srcb = dstb; dstb = tmp;
    }

    for (int idx = t; idx < G_GRAPHS * OUT_DIM; idx += 512)
        g_h[tower][idx] = srcb[idx];
}

__global__ void final_kernel(float* __restrict__ out) {
    int g = threadIdx.x;
    if (g < G_GRAPHS) {
        float s = 0.0f;
        #pragma unroll 8
        for (int k = 0; k < OUT_DIM; ++k) {
            float d = g_h[0][g * OUT_DIM + k] - g_h[1][g * OUT_DIM + k];
            s += d * d;
        }
        out[g] = sqrtf(s);
    }
}

// ---------------------------------------------------------------------------
// Host launcher
// ---------------------------------------------------------------------------
extern "C" void kernel_launch(void* const* d_in, const int* in_sizes, int n_in,
                              void* d_out, int out_size)
{
    const float* x1  = (const float*)d_in[0];
    const int*   ei1 = (const int*)  d_in[1];
    const float* ea1 = (const float*)d_in[2];
    const int*   bt1 = (const int*)  d_in[3];
    const float* x2  = (const float*)d_in[4];
    const int*   ei2 = (const int*)  d_in[5];
    const float* ea2 = (const float*)d_in[6];
    const int*   bt2 = (const int*)  d_in[7];
    const float* convW = (const float*)d_in[8];
    const float* convB = (const float*)d_in[9];
    const float* fcW1  = (const float*)d_in[10];
    const float* fcb1  = (const float*)d_in[11];
    const float* fcW   = (const float*)d_in[12];
    const float* fcb   = (const float*)d_in[13];

    const bool ACTS[6] = { true, true, false, true, true, true };

    cudaFuncSetAttribute(gemm_kernel,
                         cudaFuncAttributeMaxDynamicSharedMemorySize,
                         GEMM_SMEM_BYTES);

    const int NBN = (N_TOT + 255) / 256;
    const int NBE = (E_TOT + 255) / 256;
    const dim3 GEMM_GRID((N_TOT + 127) / 128, 2);
    const int AGG_BLOCKS = (N_TOT * 16) / 256;

    // Build unified dst-sorted CSR + norms (once; reused for 6 layers)
    zero_deg_kernel<<<NBN, 256>>>();
    deg_count_kernel<<<NBE, 256>>>(ei1, ea1, ei2, ea2);
    scan_block_kernel<<<N_SCAN_BLOCKS, SCAN_BLK>>>();
    scan_top_kernel<<<1, 256>>>();
    scan_add_kernel<<<NBN, 256>>>();
    scatter_kernel<<<NBE, 256>>>(ei1, ea1, ei2, ea2);

    // x -> fp16 (both towers)
    conv_x_kernel<<<(N_TOT * 32 + 255) / 256, 256>>>(x1, x2);

    for (int L = 0; L < 6; ++L) {
        gemm_kernel<<<GEMM_GRID, 256, GEMM_SMEM_BYTES>>>(
            convW + (size_t)L * HID * HID);
        agg_kernel<<<AGG_BLOCKS, 256>>>(convB + L * HID, ACTS[L] ? 1 : 0);
    }

    pool_zero_kernel<<<(2 * G_GRAPHS * HID + 255) / 256, 256>>>();
    pool_kernel<<<2 * POOL_BLOCKS_T, 128>>>(bt1, bt2);
    mlp_kernel<<<2, 512>>>(fcW1, fcb1, fcW, fcb);

    final_kernel<<<1, 64>>>((float*)d_out);
}

// round 12
// speedup vs baseline: 1.5327x; 1.5327x over previous
#include <cuda_runtime.h>
#include <cuda_fp16.h>
#include <math.h>

// Problem constants (fixed by the dataset)
#define N_NODES 100000
#define N_TOT   200000            // both towers fused
#define N_EDGES 1600000
#define E_TOT   3200000
#define G_GRAPHS 64
#define HID 128
#define OUT_DIM 64

#define SCAN_BLK 1024
#define N_SCAN_BLOCKS ((N_TOT + SCAN_BLK - 1) / SCAN_BLK)   // 196

// ---------------------------------------------------------------------------
// Scratch (device globals; allocation-free per harness rules)
// ---------------------------------------------------------------------------
__device__ __half g_bufAh[N_TOT * HID];     // node features (fp16), both towers
__device__ __half g_bufBh[N_TOT * HID];     // xw = x @ W (fp16)
__device__ float g_deg[N_TOT];
__device__ float g_dinv[N_TOT];
__device__ int   g_count[N_TOT];            // counts, then cursor
__device__ int   g_off[N_TOT + 1];          // CSR offsets (by global dst)
__device__ int   g_blocksum[N_SCAN_BLOCKS];
__device__ int   g_srcs[E_TOT];             // global src per sorted edge
__device__ float g_nrm[E_TOT];              // norm per sorted edge
__device__ float g_pooled[2 * G_GRAPHS * HID];
__device__ float g_cnt[2 * G_GRAPHS];
__device__ float g_h[2][G_GRAPHS * OUT_DIM];

// ---------------------------------------------------------------------------
// fp32 -> fp16 conversion of input features (both towers)
// ---------------------------------------------------------------------------
__global__ void conv_x_kernel(const float* __restrict__ x1,
                              const float* __restrict__ x2) {
    int i = blockIdx.x * blockDim.x + threadIdx.x;   // per 4 elements
    if (i < N_TOT * 32) {
        const float* x = (i < N_NODES * 32) ? x1 : x2;
        int li = (i < N_NODES * 32) ? i : (i - N_NODES * 32);
        float4 v = ((const float4*)x)[li];
        uint2 o;
        *(__half2*)&o.x = __floats2half2_rn(v.x, v.y);
        *(__half2*)&o.y = __floats2half2_rn(v.z, v.w);
        ((uint2*)g_bufAh)[i] = o;
    }
}

// ---------------------------------------------------------------------------
// Degree + counts (both edge lists, global node ids)
// ---------------------------------------------------------------------------
__global__ void zero_deg_kernel() {
    int i = blockIdx.x * blockDim.x + threadIdx.x;
    if (i < N_TOT) { g_deg[i] = 0.0f; g_count[i] = 0; }
}

__global__ void deg_count_kernel(const int* __restrict__ ei1,
                                 const float* __restrict__ ea1,
                                 const int* __restrict__ ei2,
                                 const float* __restrict__ ea2) {
    int e = blockIdx.x * blockDim.x + threadIdx.x;
    if (e < E_TOT) {
        int tower = (e >= N_EDGES) ? 1 : 0;
        int le = e - tower * N_EDGES;
        const int* ei = tower ? ei2 : ei1;
        const float* ea = tower ? ea2 : ea1;
        int di = ei[N_EDGES + le] + tower * N_NODES;
        atomicAdd(&g_deg[di], ea[le]);
        atomicAdd(&g_count[di], 1);
    }
}

// ---------------------------------------------------------------------------
// Exclusive scan of g_count -> g_off
// ---------------------------------------------------------------------------
__global__ void __launch_bounds__(SCAN_BLK)
scan_block_kernel() {
    __shared__ int s[SCAN_BLK];
    int i = blockIdx.x * SCAN_BLK + threadIdx.x;
    int v = (i < N_TOT) ? g_count[i] : 0;
    s[threadIdx.x] = v;
    __syncthreads();
    #pragma unroll
    for (int d = 1; d < SCAN_BLK; d <<= 1) {
        int t = (threadIdx.x >= d) ? s[threadIdx.x - d] : 0;
        __syncthreads();
        s[threadIdx.x] += t;
        __syncthreads();
    }
    if (i < N_TOT) g_off[i] = s[threadIdx.x] - v;
    if (threadIdx.x == SCAN_BLK - 1) g_blocksum[blockIdx.x] = s[threadIdx.x];
}

// Parallel top-level scan over 196 block sums (one block, 256 threads)
__global__ void scan_top_kernel() {
    __shared__ int s[256];
    int t = threadIdx.x;
    int v = (t < N_SCAN_BLOCKS) ? g_blocksum[t] : 0;
    s[t] = v;
    __syncthreads();
    #pragma unroll
    for (int d = 1; d < 256; d <<= 1) {
        int tv = (t >= d) ? s[t - d] : 0;
        __syncthreads();
        s[t] += tv;
        __syncthreads();
    }
    if (t < N_SCAN_BLOCKS) g_blocksum[t] = s[t] - v;   // exclusive
    if (t == 255) g_off[N_TOT] = s[255];
}

// also computes dinv (deg is final by now)
__global__ void scan_add_kernel() {
    int i = blockIdx.x * blockDim.x + threadIdx.x;
    if (i < N_TOT) {
        int o = g_off[i] + g_blocksum[i >> 10];
        g_off[i] = o;
        g_count[i] = o;
        g_dinv[i] = rsqrtf(g_deg[i] + 1.0f);
    }
}

__global__ void scatter_kernel(const int* __restrict__ ei1,
                               const float* __restrict__ ea1,
                               const int* __restrict__ ei2,
                               const float* __restrict__ ea2) {
    int e = blockIdx.x * blockDim.x + threadIdx.x;
    if (e < E_TOT) {
        int tower = (e >= N_EDGES) ? 1 : 0;
        int le = e - tower * N_EDGES;
        const int* ei = tower ? ei2 : ei1;
        const float* ea = tower ? ea2 : ea1;
        int si = ei[le] + tower * N_NODES;
        int di = ei[N_EDGES + le] + tower * N_NODES;
        int pos = atomicAdd(&g_count[di], 1);
        g_srcs[pos] = si;
        g_nrm[pos]  = g_dinv[si] * ea[le] * g_dinv[di];
    }
}

// ---------------------------------------------------------------------------
// GEMM (HFMA2, pre-splatted X): bufB[n,c] = sum_k bufA[n,k] * W[k,c]
// Block tile 128(M) x 64(N); grid = (row blocks, 2 col halves).
// fp16 accumulate over chunks of 8 k, promoted to fp32.  (At HFMA2 issue floor.)
// ---------------------------------------------------------------------------
#define WSTR2 32
#define GEMM_SMEM_BYTES (HID * 128 * 4 + HID * WSTR2 * 4)   // 64KB + 16KB

__global__ void __launch_bounds__(256, 2)
gemm_kernel(const float* __restrict__ W)
{
    extern __shared__ __half2 smem2[];
    __half2* sXd = smem2;               // [k*128 + r], splatted
    __half2* sW2 = smem2 + HID * 128;   // [k*WSTR2 + cp]

    const int tid  = threadIdx.x;
    const int row0 = blockIdx.x * 128;
    const int gy   = blockIdx.y;        // column half

    // Load W slice (128 k x 64 cols), fp32 -> half2 col-pairs
    {
        const float4* W4 = (const float4*)W;
        #pragma unroll
        for (int i = 0; i < 8; ++i) {
            int idx = tid + i * 256;     // 0..2047
            int k  = idx >> 4;
            int c4 = idx & 15;
            float4 v = W4[k * 32 + gy * 16 + c4];
            uint2 o;
            *(__half2*)&o.x = __floats2half2_rn(v.x, v.y);
            *(__half2*)&o.y = __floats2half2_rn(v.z, v.w);
            *(uint2*)&sW2[k * WSTR2 + c4 * 2] = o;
        }
    }

    // Load X tile (128 rows x 128 k fp16), splat each value into sXd[k][r]
    {
        const uint4* Xg = (const uint4*)g_bufAh;   // 8 halfs per uint4
        #pragma unroll
        for (int i = 0; i < 8; ++i) {
            int idx = tid + i * 256;      // 0..2047
            int r   = idx & 127;
            int k8  = idx >> 7;           // 0..15, chunk of 8 k
            int grow = row0 + r;
            uint4 u = make_uint4(0u, 0u, 0u, 0u);
            if (grow < N_TOT) u = Xg[(size_t)grow * 16 + k8];
            const __half* ph = (const __half*)&u;
            #pragma unroll
            for (int t = 0; t < 8; ++t)
                sXd[(k8 * 8 + t) * 128 + r] = __half2half2(ph[t]);
        }
    }
    __syncthreads();

    const int tx = tid & 15;   // cols tx*4 .. tx*4+3 within the 64-col slice
    const int ty = tid >> 4;   // rows ty*4 and 64+ty*4

    float accf[8][4];
    #pragma unroll
    for (int i = 0; i < 8; ++i)
        #pragma unroll
        for (int j = 0; j < 4; ++j) accf[i][j] = 0.0f;

    #pragma unroll
    for (int kc = 0; kc < 16; ++kc) {        // 16 chunks of 8 k
        __half2 acc2[8][2];
        #pragma unroll
        for (int i = 0; i < 8; ++i) {
            acc2[i][0] = __floats2half2_rn(0.0f, 0.0f);
            acc2[i][1] = __floats2half2_rn(0.0f, 0.0f);
        }

        #pragma unroll
        for (int kk = 0; kk < 8; ++kk) {
            int k = kc * 8 + kk;
            uint4 xva = *(const uint4*)&sXd[k * 128 + ty * 4];
            uint4 xvb = *(const uint4*)&sXd[k * 128 + 64 + ty * 4];
            const __half2* pa = (const __half2*)&xva;
            const __half2* pb = (const __half2*)&xvb;

            __half2 wr0 = sW2[k * WSTR2 + tx * 2];
            __half2 wr1 = sW2[k * WSTR2 + tx * 2 + 1];

            #pragma unroll
            for (int i = 0; i < 4; ++i) {
                acc2[i][0] = __hfma2(pa[i], wr0, acc2[i][0]);
                acc2[i][1] = __hfma2(pa[i], wr1, acc2[i][1]);
                acc2[i + 4][0] = __hfma2(pb[i], wr0, acc2[i + 4][0]);
                acc2[i + 4][1] = __hfma2(pb[i], wr1, acc2[i + 4][1]);
            }
        }

        #pragma unroll
        for (int i = 0; i < 8; ++i) {
            float2 f0 = __half22float2(acc2[i][0]);
            float2 f1 = __half22float2(acc2[i][1]);
            accf[i][0] += f0.x; accf[i][1] += f0.y;
            accf[i][2] += f1.x; accf[i][3] += f1.y;
        }
    }

    // Epilogue: fp32 acc -> fp16 global
    const int col0 = gy * 64 + tx * 4;
    #pragma unroll
    for (int i = 0; i < 8; ++i) {
        int r = (i < 4) ? (ty * 4 + i) : (64 + ty * 4 + i - 4);
        int grow = row0 + r;
        if (grow < N_TOT) {
            uint2 o;
            *(__half2*)&o.x = __floats2half2_rn(accf[i][0], accf[i][1]);
            *(__half2*)&o.y = __floats2half2_rn(accf[i][2], accf[i][3]);
            *(uint2*)&g_bufBh[(size_t)grow * HID + col0] = o;
        }
    }
}

// ---------------------------------------------------------------------------
// Aggregation: HALF-WARP per destination node (16 lanes x 8 channels).
// (Exact R10 configuration — 2-edge unroll, separate srcs/nrm arrays.)
// out = act( bias + dinv*dinv * xw[self] + sum_j nrm[j] * xw[src[j]] )
// ---------------------------------------------------------------------------
__device__ __forceinline__ void fma8(float* a, const uint4& v, float n) {
    const __half2* p = (const __half2*)&v;
    float2 q0 = __half22float2(p[0]);
    float2 q1 = __half22float2(p[1]);
    float2 q2 = __half22float2(p[2]);
    float2 q3 = __half22float2(p[3]);
    a[0] += n * q0.x; a[1] += n * q0.y;
    a[2] += n * q1.x; a[3] += n * q1.y;
    a[4] += n * q2.x; a[5] += n * q2.y;
    a[6] += n * q3.x; a[7] += n * q3.y;
}

__global__ void __launch_bounds__(256)
agg_kernel(const float* __restrict__ bias, int act)
{
    int node = (blockIdx.x * blockDim.x + threadIdx.x) >> 4;  // half-warp id
    int ln   = threadIdx.x & 15;
    if (node >= N_TOT) return;

    const uint4* xw = (const uint4*)g_bufBh;

    int beg = g_off[node];
    int end = g_off[node + 1];

    float s = g_dinv[node];
    s = s * s;
    float4 b0 = ((const float4*)bias)[ln * 2];
    float4 b1 = ((const float4*)bias)[ln * 2 + 1];
    float a[8] = { b0.x, b0.y, b0.z, b0.w, b1.x, b1.y, b1.z, b1.w };

    uint4 self = xw[(size_t)node * 16 + ln];
    fma8(a, self, s);

    int j = beg;
    for (; j + 1 < end; j += 2) {
        int   s0 = g_srcs[j];
        int   s1 = g_srcs[j + 1];
        float n0 = g_nrm[j];
        float n1 = g_nrm[j + 1];
        uint4 v0 = xw[(size_t)s0 * 16 + ln];
        uint4 v1 = xw[(size_t)s1 * 16 + ln];
        fma8(a, v0, n0);
        fma8(a, v1, n1);
    }
    if (j < end) {
        int   s0 = g_srcs[j];
        float n0 = g_nrm[j];
        uint4 v0 = xw[(size_t)s0 * 16 + ln];
        fma8(a, v0, n0);
    }

    if (act) {
        #pragma unroll
        for (int i = 0; i < 8; ++i) a[i] = tanhf(a[i]);
    }
    uint4 o;
    *(__half2*)&o.x = __floats2half2_rn(a[0], a[1]);
    *(__half2*)&o.y = __floats2half2_rn(a[2], a[3]);
    *(__half2*)&o.z = __floats2half2_rn(a[4], a[5]);
    *(__half2*)&o.w = __floats2half2_rn(a[6], a[7]);
    ((uint4*)g_bufAh)[(size_t)node * 16 + ln] = o;
}

// ---------------------------------------------------------------------------
// Global mean pool (batch sorted per tower). grid = 2 * POOL_BLOCKS_T.
// ---------------------------------------------------------------------------
#define POOL_CHUNK 128
#define POOL_BLOCKS_T ((N_NODES + POOL_CHUNK - 1) / POOL_CHUNK)

__global__ void pool_zero_kernel() {
    int i = blockIdx.x * blockDim.x + threadIdx.x;
    if (i < 2 * G_GRAPHS * HID) g_pooled[i] = 0.0f;
    if (i < 2 * G_GRAPHS) g_cnt[i] = 0.0f;
}

__global__ void pool_kernel(const int* __restrict__ batch1,
                            const int* __restrict__ batch2) {
    int tower = (blockIdx.x >= POOL_BLOCKS_T) ? 1 : 0;
    const int* batch = tower ? batch2 : batch1;
    int blk = blockIdx.x - tower * POOL_BLOCKS_T;
    int c  = threadIdx.x;
    int n0 = blk * POOL_CHUNK;
    int n1 = n0 + POOL_CHUNK;
    if (n1 > N_NODES) n1 = N_NODES;
    if (n0 >= N_NODES) return;

    int gbase = tower * G_GRAPHS;
    size_t nodeoff = (size_t)tower * N_NODES;

    float acc = 0.0f;
    int cur = batch[n0];
    int run = 0;
    for (int n = n0; n < n1; ++n) {
        int g = batch[n];
        if (g != cur) {
            atomicAdd(&g_pooled[(gbase + cur) * HID + c], acc);
            if (c == 0) atomicAdd(&g_cnt[gbase + cur], (float)run);
            acc = 0.0f; run = 0; cur = g;
        }
        acc += __half2float(g_bufAh[(nodeoff + n) * HID + c]);
        run++;
    }
    atomicAdd(&g_pooled[(gbase + cur) * HID + c], acc);
    if (c == 0) atomicAdd(&g_cnt[gbase + cur], (float)run);
}

// ---------------------------------------------------------------------------
// MLP head: fc1 (128->64, relu) + 5 x fc (64->64, relu). grid = 2 (towers).
// ---------------------------------------------------------------------------
__global__ void __launch_bounds__(512)
mlp_kernel(const float* __restrict__ fcW1, const float* __restrict__ fcb1,
           const float* __restrict__ fcW,  const float* __restrict__ fcb)
{
    __shared__ float ha[G_GRAPHS * OUT_DIM];
    __shared__ float hb[G_GRAPHS * OUT_DIM];
    int t = threadIdx.x;
    int tower = blockIdx.x;
    int gbase = tower * G_GRAPHS;

    for (int idx = t; idx < G_GRAPHS * OUT_DIM; idx += 512) {
        int g = idx >> 6, o = idx & 63;
        float ic = g_cnt[gbase + g];
        ic = 1.0f / fmaxf(ic, 1.0f);
        float s = fcb1[o];
        #pragma unroll 4
        for (int k = 0; k < HID; ++k)
            s += g_pooled[(gbase + g) * HID + k] * ic * fcW1[k * OUT_DIM + o];
        ha[idx] = fmaxf(s, 0.0f);
    }
    __syncthreads();

    float* srcb = ha;
    float* dstb = hb;
    for (int L = 0; L < 5; ++L) {
        const float* Wp = fcW + L * OUT_DIM * OUT_DIM;
        const float* bp = fcb + L * OUT_DIM;
        for (int idx = t; idx < G_GRAPHS * OUT_DIM; idx += 512) {
            int g = idx >> 6, o = idx & 63;
            float s = bp[o];
            #pragma unroll 8
            for (int k = 0; k < OUT_DIM; ++k)
                s += srcb[g * OUT_DIM + k] * Wp[k * OUT_DIM + o];
            dstb[idx] = fmaxf(s, 0.0f);
        }
        __syncthreads();
        float* tmp = srcb; srcb = dstb; dstb = tmp;
    }

    for (int idx = t; idx < G_GRAPHS * OUT_DIM; idx += 512)
        g_h[tower][idx] = srcb[idx];
}

__global__ void final_kernel(float* __restrict__ out) {
    int g = threadIdx.x;
    if (g < G_GRAPHS) {
        float s = 0.0f;
        #pragma unroll 8
        for (int k = 0; k < OUT_DIM; ++k) {
            float d = g_h[0][g * OUT_DIM + k] - g_h[1][g * OUT_DIM + k];
            s += d * d;
        }
        out[g] = sqrtf(s);
    }
}

// ---------------------------------------------------------------------------
// Host launcher
// ---------------------------------------------------------------------------
extern "C" void kernel_launch(void* const* d_in, const int* in_sizes, int n_in,
                              void* d_out, int out_size)
{
    const float* x1  = (const float*)d_in[0];
    const int*   ei1 = (const int*)  d_in[1];
    const float* ea1 = (const float*)d_in[2];
    const int*   bt1 = (const int*)  d_in[3];
    const float* x2  = (const float*)d_in[4];
    const int*   ei2 = (const int*)  d_in[5];
    const float* ea2 = (const float*)d_in[6];
    const int*   bt2 = (const int*)  d_in[7];
    const float* convW = (const float*)d_in[8];
    const float* convB = (const float*)d_in[9];
    const float* fcW1  = (const float*)d_in[10];
    const float* fcb1  = (const float*)d_in[11];
    const float* fcW   = (const float*)d_in[12];
    const float* fcb   = (const float*)d_in[13];

    const bool ACTS[6] = { true, true, false, true, true, true };

    cudaFuncSetAttribute(gemm_kernel,
                         cudaFuncAttributeMaxDynamicSharedMemorySize,
                         GEMM_SMEM_BYTES);

    const int NBN = (N_TOT + 255) / 256;
    const int NBE = (E_TOT + 255) / 256;
    const dim3 GEMM_GRID((N_TOT + 127) / 128, 2);
    const int AGG_BLOCKS = (N_TOT * 16) / 256;

    // Build unified dst-sorted CSR + norms (once; reused for 6 layers)
    zero_deg_kernel<<<NBN, 256>>>();
    deg_count_kernel<<<NBE, 256>>>(ei1, ea1, ei2, ea2);
    scan_block_kernel<<<N_SCAN_BLOCKS, SCAN_BLK>>>();
    scan_top_kernel<<<1, 256>>>();
    scan_add_kernel<<<NBN, 256>>>();
    scatter_kernel<<<NBE, 256>>>(ei1, ea1, ei2, ea2);

    // x -> fp16 (both towers)
    conv_x_kernel<<<(N_TOT * 32 + 255) / 256, 256>>>(x1, x2);

    for (int L = 0; L < 6; ++L) {
        gemm_kernel<<<GEMM_GRID, 256, GEMM_SMEM_BYTES>>>(
            convW + (size_t)L * HID * HID);
        agg_kernel<<<AGG_BLOCKS, 256>>>(convB + L * HID, ACTS[L] ? 1 : 0);
    }

    pool_zero_kernel<<<(2 * G_GRAPHS * HID + 255) / 256, 256>>>();
    pool_kernel<<<2 * POOL_BLOCKS_T, 128>>>(bt1, bt2);
    mlp_kernel<<<2, 512>>>(fcW1, fcb1, fcW, fcb);

    final_kernel<<<1, 64>>>((float*)d_out);
}

// round 13
// speedup vs baseline: 1.6131x; 1.0524x over previous
#include <cuda_runtime.h>
#include <cuda_fp16.h>
#include <math.h>

// Problem constants (fixed by the dataset)
#define N_NODES 100000
#define N_TOT   200000            // both towers fused
#define N_EDGES 1600000
#define E_TOT   3200000
#define G_GRAPHS 64
#define HID 128
#define OUT_DIM 64

#define SCAN_BLK 1024
#define N_SCAN_BLOCKS ((N_TOT + SCAN_BLK - 1) / SCAN_BLK)   // 196

// ---------------------------------------------------------------------------
// Scratch (device globals; allocation-free per harness rules)
// ---------------------------------------------------------------------------
__device__ __half g_bufAh[N_TOT * HID];     // node features (fp16), both towers
__device__ __half g_bufBh[N_TOT * HID];     // xw = x @ W (fp16)
__device__ float g_deg[N_TOT];
__device__ float g_dinv[N_TOT];
__device__ int   g_count[N_TOT];            // counts, then cursor
__device__ int   g_off[N_TOT + 1];          // CSR offsets (by global dst)
__device__ int   g_blocksum[N_SCAN_BLOCKS];
__device__ int   g_srcs[E_TOT];             // global src per sorted edge
__device__ float g_nrm[E_TOT];              // norm per sorted edge
__device__ float g_pooled[2 * G_GRAPHS * HID];
__device__ float g_cnt[2 * G_GRAPHS];
__device__ float g_h[2][G_GRAPHS * OUT_DIM];

// ---------------------------------------------------------------------------
// fp32 -> fp16 conversion of input features (both towers)
// Also zeroes the pool accumulators (independent, saves a launch).
// ---------------------------------------------------------------------------
__global__ void conv_x_kernel(const float* __restrict__ x1,
                              const float* __restrict__ x2) {
    int i = blockIdx.x * blockDim.x + threadIdx.x;   // per 4 elements
    if (i < N_TOT * 32) {
        const float* x = (i < N_NODES * 32) ? x1 : x2;
        int li = (i < N_NODES * 32) ? i : (i - N_NODES * 32);
        float4 v = ((const float4*)x)[li];
        uint2 o;
        *(__half2*)&o.x = __floats2half2_rn(v.x, v.y);
        *(__half2*)&o.y = __floats2half2_rn(v.z, v.w);
        ((uint2*)g_bufAh)[i] = o;
    }
    if (i < 2 * G_GRAPHS * HID) g_pooled[i] = 0.0f;
    if (i < 2 * G_GRAPHS) g_cnt[i] = 0.0f;
}

// ---------------------------------------------------------------------------
// Degree + counts (both edge lists, global node ids)
// ---------------------------------------------------------------------------
__global__ void zero_deg_kernel() {
    int i = blockIdx.x * blockDim.x + threadIdx.x;
    if (i < N_TOT) { g_deg[i] = 0.0f; g_count[i] = 0; }
}

__global__ void deg_count_kernel(const int* __restrict__ ei1,
                                 const float* __restrict__ ea1,
                                 const int* __restrict__ ei2,
                                 const float* __restrict__ ea2) {
    int e = blockIdx.x * blockDim.x + threadIdx.x;
    if (e < E_TOT) {
        int tower = (e >= N_EDGES) ? 1 : 0;
        int le = e - tower * N_EDGES;
        const int* ei = tower ? ei2 : ei1;
        const float* ea = tower ? ea2 : ea1;
        int di = ei[N_EDGES + le] + tower * N_NODES;
        atomicAdd(&g_deg[di], ea[le]);
        atomicAdd(&g_count[di], 1);
    }
}

// ---------------------------------------------------------------------------
// Exclusive scan of g_count -> g_off
// ---------------------------------------------------------------------------
__global__ void __launch_bounds__(SCAN_BLK)
scan_block_kernel() {
    __shared__ int s[SCAN_BLK];
    int i = blockIdx.x * SCAN_BLK + threadIdx.x;
    int v = (i < N_TOT) ? g_count[i] : 0;
    s[threadIdx.x] = v;
    __syncthreads();
    #pragma unroll
    for (int d = 1; d < SCAN_BLK; d <<= 1) {
        int t = (threadIdx.x >= d) ? s[threadIdx.x - d] : 0;
        __syncthreads();
        s[threadIdx.x] += t;
        __syncthreads();
    }
    if (i < N_TOT) g_off[i] = s[threadIdx.x] - v;
    if (threadIdx.x == SCAN_BLK - 1) g_blocksum[blockIdx.x] = s[threadIdx.x];
}

// Parallel top-level scan over 196 block sums (one block, 256 threads)
__global__ void scan_top_kernel() {
    __shared__ int s[256];
    int t = threadIdx.x;
    int v = (t < N_SCAN_BLOCKS) ? g_blocksum[t] : 0;
    s[t] = v;
    __syncthreads();
    #pragma unroll
    for (int d = 1; d < 256; d <<= 1) {
        int tv = (t >= d) ? s[t - d] : 0;
        __syncthreads();
        s[t] += tv;
        __syncthreads();
    }
    if (t < N_SCAN_BLOCKS) g_blocksum[t] = s[t] - v;   // exclusive
    if (t == 255) g_off[N_TOT] = s[255];
}

// also computes dinv (deg is final by now)
__global__ void scan_add_kernel() {
    int i = blockIdx.x * blockDim.x + threadIdx.x;
    if (i < N_TOT) {
        int o = g_off[i] + g_blocksum[i >> 10];
        g_off[i] = o;
        g_count[i] = o;
        g_dinv[i] = rsqrtf(g_deg[i] + 1.0f);
    }
}

__global__ void scatter_kernel(const int* __restrict__ ei1,
                               const float* __restrict__ ea1,
                               const int* __restrict__ ei2,
                               const float* __restrict__ ea2) {
    int e = blockIdx.x * blockDim.x + threadIdx.x;
    if (e < E_TOT) {
        int tower = (e >= N_EDGES) ? 1 : 0;
        int le = e - tower * N_EDGES;
        const int* ei = tower ? ei2 : ei1;
        const float* ea = tower ? ea2 : ea1;
        int si = ei[le] + tower * N_NODES;
        int di = ei[N_EDGES + le] + tower * N_NODES;
        int pos = atomicAdd(&g_count[di], 1);
        g_srcs[pos] = si;
        g_nrm[pos]  = g_dinv[si] * ea[le] * g_dinv[di];
    }
}

// ---------------------------------------------------------------------------
// GEMM (HFMA2, pre-splatted X): bufB[n,c] = sum_k bufA[n,k] * W[k,c]
// Block tile 128(M) x 64(N); grid = (row blocks, 2 col halves).
// fp16 accumulate over chunks of 16 k, promoted to fp32.
// ---------------------------------------------------------------------------
#define WSTR2 32
#define GEMM_SMEM_BYTES (HID * 128 * 4 + HID * WSTR2 * 4)   // 64KB + 16KB

__global__ void __launch_bounds__(256, 2)
gemm_kernel(const float* __restrict__ W)
{
    extern __shared__ __half2 smem2[];
    __half2* sXd = smem2;               // [k*128 + r], splatted
    __half2* sW2 = smem2 + HID * 128;   // [k*WSTR2 + cp]

    const int tid  = threadIdx.x;
    const int row0 = blockIdx.x * 128;
    const int gy   = blockIdx.y;        // column half

    // Load W slice (128 k x 64 cols), fp32 -> half2 col-pairs
    {
        const float4* W4 = (const float4*)W;
        #pragma unroll
        for (int i = 0; i < 8; ++i) {
            int idx = tid + i * 256;     // 0..2047
            int k  = idx >> 4;
            int c4 = idx & 15;
            float4 v = W4[k * 32 + gy * 16 + c4];
            uint2 o;
            *(__half2*)&o.x = __floats2half2_rn(v.x, v.y);
            *(__half2*)&o.y = __floats2half2_rn(v.z, v.w);
            *(uint2*)&sW2[k * WSTR2 + c4 * 2] = o;
        }
    }

    // Load X tile (128 rows x 128 k fp16), splat each value into sXd[k][r]
    {
        const uint4* Xg = (const uint4*)g_bufAh;   // 8 halfs per uint4
        #pragma unroll
        for (int i = 0; i < 8; ++i) {
            int idx = tid + i * 256;      // 0..2047
            int r   = idx & 127;
            int k8  = idx >> 7;           // 0..15, chunk of 8 k
            int grow = row0 + r;
            uint4 u = make_uint4(0u, 0u, 0u, 0u);
            if (grow < N_TOT) u = Xg[(size_t)grow * 16 + k8];
            const __half* ph = (const __half*)&u;
            #pragma unroll
            for (int t = 0; t < 8; ++t)
                sXd[(k8 * 8 + t) * 128 + r] = __half2half2(ph[t]);
        }
    }
    __syncthreads();

    const int tx = tid & 15;   // cols tx*4 .. tx*4+3 within the 64-col slice
    const int ty = tid >> 4;   // rows ty*4 and 64+ty*4

    float accf[8][4];
    #pragma unroll
    for (int i = 0; i < 8; ++i)
        #pragma unroll
        for (int j = 0; j < 4; ++j) accf[i][j] = 0.0f;

    #pragma unroll
    for (int kc = 0; kc < 8; ++kc) {        // 8 chunks of 16 k
        __half2 acc2[8][2];
        #pragma unroll
        for (int i = 0; i < 8; ++i) {
            acc2[i][0] = __floats2half2_rn(0.0f, 0.0f);
            acc2[i][1] = __floats2half2_rn(0.0f, 0.0f);
        }

        #pragma unroll
        for (int kk = 0; kk < 16; ++kk) {
            int k = kc * 16 + kk;
            uint4 xva = *(const uint4*)&sXd[k * 128 + ty * 4];
            uint4 xvb = *(const uint4*)&sXd[k * 128 + 64 + ty * 4];
            const __half2* pa = (const __half2*)&xva;
            const __half2* pb = (const __half2*)&xvb;

            __half2 wr0 = sW2[k * WSTR2 + tx * 2];
            __half2 wr1 = sW2[k * WSTR2 + tx * 2 + 1];

            #pragma unroll
            for (int i = 0; i < 4; ++i) {
                acc2[i][0] = __hfma2(pa[i], wr0, acc2[i][0]);
                acc2[i][1] = __hfma2(pa[i], wr1, acc2[i][1]);
                acc2[i + 4][0] = __hfma2(pb[i], wr0, acc2[i + 4][0]);
                acc2[i + 4][1] = __hfma2(pb[i], wr1, acc2[i + 4][1]);
            }
        }

        #pragma unroll
        for (int i = 0; i < 8; ++i) {
            float2 f0 = __half22float2(acc2[i][0]);
            float2 f1 = __half22float2(acc2[i][1]);
            accf[i][0] += f0.x; accf[i][1] += f0.y;
            accf[i][2] += f1.x; accf[i][3] += f1.y;
        }
    }

    // Epilogue: fp32 acc -> fp16 global
    const int col0 = gy * 64 + tx * 4;
    #pragma unroll
    for (int i = 0; i < 8; ++i) {
        int r = (i < 4) ? (ty * 4 + i) : (64 + ty * 4 + i - 4);
        int grow = row0 + r;
        if (grow < N_TOT) {
            uint2 o;
            *(__half2*)&o.x = __floats2half2_rn(accf[i][0], accf[i][1]);
            *(__half2*)&o.y = __floats2half2_rn(accf[i][2], accf[i][3]);
            *(uint2*)&g_bufBh[(size_t)grow * HID + col0] = o;
        }
    }
}

// ---------------------------------------------------------------------------
// Aggregation: HALF-WARP per destination node (16 lanes x 8 channels).
// (Frozen R10/R12 configuration — 2-edge unroll, separate srcs/nrm arrays.)
// out = act( bias + dinv*dinv * xw[self] + sum_j nrm[j] * xw[src[j]] )
// ---------------------------------------------------------------------------
__device__ __forceinline__ void fma8(float* a, const uint4& v, float n) {
    const __half2* p = (const __half2*)&v;
    float2 q0 = __half22float2(p[0]);
    float2 q1 = __half22float2(p[1]);
    float2 q2 = __half22float2(p[2]);
    float2 q3 = __half22float2(p[3]);
    a[0] += n * q0.x; a[1] += n * q0.y;
    a[2] += n * q1.x; a[3] += n * q1.y;
    a[4] += n * q2.x; a[5] += n * q2.y;
    a[6] += n * q3.x; a[7] += n * q3.y;
}

__global__ void __launch_bounds__(256)
agg_kernel(const float* __restrict__ bias, int act)
{
    int node = (blockIdx.x * blockDim.x + threadIdx.x) >> 4;  // half-warp id
    int ln   = threadIdx.x & 15;
    if (node >= N_TOT) return;

    const uint4* xw = (const uint4*)g_bufBh;

    int beg = g_off[node];
    int end = g_off[node + 1];

    float s = g_dinv[node];
    s = s * s;
    float4 b0 = ((const float4*)bias)[ln * 2];
    float4 b1 = ((const float4*)bias)[ln * 2 + 1];
    float a[8] = { b0.x, b0.y, b0.z, b0.w, b1.x, b1.y, b1.z, b1.w };

    uint4 self = xw[(size_t)node * 16 + ln];
    fma8(a, self, s);

    int j = beg;
    for (; j + 1 < end; j += 2) {
        int   s0 = g_srcs[j];
        int   s1 = g_srcs[j + 1];
        float n0 = g_nrm[j];
        float n1 = g_nrm[j + 1];
        uint4 v0 = xw[(size_t)s0 * 16 + ln];
        uint4 v1 = xw[(size_t)s1 * 16 + ln];
        fma8(a, v0, n0);
        fma8(a, v1, n1);
    }
    if (j < end) {
        int   s0 = g_srcs[j];
        float n0 = g_nrm[j];
        uint4 v0 = xw[(size_t)s0 * 16 + ln];
        fma8(a, v0, n0);
    }

    if (act) {
        #pragma unroll
        for (int i = 0; i < 8; ++i) a[i] = tanhf(a[i]);
    }
    uint4 o;
    *(__half2*)&o.x = __floats2half2_rn(a[0], a[1]);
    *(__half2*)&o.y = __floats2half2_rn(a[2], a[3]);
    *(__half2*)&o.z = __floats2half2_rn(a[4], a[5]);
    *(__half2*)&o.w = __floats2half2_rn(a[6], a[7]);
    ((uint4*)g_bufAh)[(size_t)node * 16 + ln] = o;
}

// ---------------------------------------------------------------------------
// Global mean pool (batch sorted per tower). grid = 2 * POOL_BLOCKS_T.
// ---------------------------------------------------------------------------
#define POOL_CHUNK 128
#define POOL_BLOCKS_T ((N_NODES + POOL_CHUNK - 1) / POOL_CHUNK)

__global__ void pool_kernel(const int* __restrict__ batch1,
                            const int* __restrict__ batch2) {
    int tower = (blockIdx.x >= POOL_BLOCKS_T) ? 1 : 0;
    const int* batch = tower ? batch2 : batch1;
    int blk = blockIdx.x - tower * POOL_BLOCKS_T;
    int c  = threadIdx.x;
    int n0 = blk * POOL_CHUNK;
    int n1 = n0 + POOL_CHUNK;
    if (n1 > N_NODES) n1 = N_NODES;
    if (n0 >= N_NODES) return;

    int gbase = tower * G_GRAPHS;
    size_t nodeoff = (size_t)tower * N_NODES;

    float acc = 0.0f;
    int cur = batch[n0];
    int run = 0;
    for (int n = n0; n < n1; ++n) {
        int g = batch[n];
        if (g != cur) {
            atomicAdd(&g_pooled[(gbase + cur) * HID + c], acc);
            if (c == 0) atomicAdd(&g_cnt[gbase + cur], (float)run);
            acc = 0.0f; run = 0; cur = g;
        }
        acc += __half2float(g_bufAh[(nodeoff + n) * HID + c]);
        run++;
    }
    atomicAdd(&g_pooled[(gbase + cur) * HID + c], acc);
    if (c == 0) atomicAdd(&g_cnt[gbase + cur], (float)run);
}

// ---------------------------------------------------------------------------
// MLP head: fc1 (128->64, relu) + 5 x fc (64->64, relu). grid = 2 (towers).
// ---------------------------------------------------------------------------
__global__ void __launch_bounds__(512)
mlp_kernel(const float* __restrict__ fcW1, const float* __restrict__ fcb1,
           const float* __restrict__ fcW,  const float* __restrict__ fcb)
{
    __shared__ float ha[G_GRAPHS * OUT_DIM];
    __shared__ float hb[G_GRAPHS * OUT_DIM];
    int t = threadIdx.x;
    int tower = blockIdx.x;
    int gbase = tower * G_GRAPHS;

    for (int idx = t; idx < G_GRAPHS * OUT_DIM; idx += 512) {
        int g = idx >> 6, o = idx & 63;
        float ic = g_cnt[gbase + g];
        ic = 1.0f / fmaxf(ic, 1.0f);
        float s = fcb1[o];
        #pragma unroll 4
        for (int k = 0; k < HID; ++k)
            s += g_pooled[(gbase + g) * HID + k] * ic * fcW1[k * OUT_DIM + o];
        ha[idx] = fmaxf(s, 0.0f);
    }
    __syncthreads();

    float* srcb = ha;
    float* dstb = hb;
    for (int L = 0; L < 5; ++L) {
        const float* Wp = fcW + L * OUT_DIM * OUT_DIM;
        const float* bp = fcb + L * OUT_DIM;
        for (int idx = t; idx < G_GRAPHS * OUT_DIM; idx += 512) {
            int g = idx >> 6, o = idx & 63;
            float s = bp[o];
            #pragma unroll 8
            for (int k = 0; k < OUT_DIM; ++k)
                s += srcb[g * OUT_DIM + k] * Wp[k * OUT_DIM + o];
            dstb[idx] = fmaxf(s, 0.0f);
        }
        __syncthreads();
        float* tmp = srcb; srcb = dstb; dstb = tmp;
    }

    for (int idx = t; idx < G_GRAPHS * OUT_DIM; idx += 512)
        g_h[tower][idx] = srcb[idx];
}

__global__ void final_kernel(float* __restrict__ out) {
    int g = threadIdx.x;
    if (g < G_GRAPHS) {
        float s = 0.0f;
        #pragma unroll 8
        for (int k = 0; k < OUT_DIM; ++k) {
            float d = g_h[0][g * OUT_DIM + k] - g_h[1][g * OUT_DIM + k];
            s += d * d;
        }
        out[g] = sqrtf(s);
    }
}

// ---------------------------------------------------------------------------
// Host launcher
// ---------------------------------------------------------------------------
extern "C" void kernel_launch(void* const* d_in, const int* in_sizes, int n_in,
                              void* d_out, int out_size)
{
    const float* x1  = (const float*)d_in[0];
    const int*   ei1 = (const int*)  d_in[1];
    const float* ea1 = (const float*)d_in[2];
    const int*   bt1 = (const int*)  d_in[3];
    const float* x2  = (const float*)d_in[4];
    const int*   ei2 = (const int*)  d_in[5];
    const float* ea2 = (const float*)d_in[6];
    const int*   bt2 = (const int*)  d_in[7];
    const float* convW = (const float*)d_in[8];
    const float* convB = (const float*)d_in[9];
    const float* fcW1  = (const float*)d_in[10];
    const float* fcb1  = (const float*)d_in[11];
    const float* fcW   = (const float*)d_in[12];
    const float* fcb   = (const float*)d_in[13];

    const bool ACTS[6] = { true, true, false, true, true, true };

    cudaFuncSetAttribute(gemm_kernel,
                         cudaFuncAttributeMaxDynamicSharedMemorySize,
                         GEMM_SMEM_BYTES);

    const int NBN = (N_TOT + 255) / 256;
    const int NBE = (E_TOT + 255) / 256;
    const dim3 GEMM_GRID((N_TOT + 127) / 128, 2);
    const int AGG_BLOCKS = (N_TOT * 16) / 256;

    // Build unified dst-sorted CSR + norms (once; reused for 6 layers)
    zero_deg_kernel<<<NBN, 256>>>();
    deg_count_kernel<<<NBE, 256>>>(ei1, ea1, ei2, ea2);
    scan_block_kernel<<<N_SCAN_BLOCKS, SCAN_BLK>>>();
    scan_top_kernel<<<1, 256>>>();
    scan_add_kernel<<<NBN, 256>>>();
    scatter_kernel<<<NBE, 256>>>(ei1, ea1, ei2, ea2);

    // x -> fp16 (both towers) + pool accumulator zeroing
    conv_x_kernel<<<(N_TOT * 32 + 255) / 256, 256>>>(x1, x2);

    for (int L = 0; L < 6; ++L) {
        gemm_kernel<<<GEMM_GRID, 256, GEMM_SMEM_BYTES>>>(
            convW + (size_t)L * HID * HID);
        agg_kernel<<<AGG_BLOCKS, 256>>>(convB + L * HID, ACTS[L] ? 1 : 0);
    }

    pool_kernel<<<2 * POOL_BLOCKS_T, 128>>>(bt1, bt2);
    mlp_kernel<<<2, 512>>>(fcW1, fcb1, fcW, fcb);

    final_kernel<<<1, 64>>>((float*)d_out);
}

// round 14
// speedup vs baseline: 1.6376x; 1.0152x over previous
#include <cuda_runtime.h>
#include <cuda_fp16.h>
#include <math.h>

// Problem constants (fixed by the dataset)
#define N_NODES 100000
#define N_TOT   200000            // both towers fused
#define N_EDGES 1600000
#define E_TOT   3200000
#define G_GRAPHS 64
#define HID 128
#define OUT_DIM 64

#define SCAN_BLK 1024
#define N_SCAN_BLOCKS ((N_TOT + SCAN_BLK - 1) / SCAN_BLK)   // 196

// ---------------------------------------------------------------------------
// Scratch (device globals; allocation-free per harness rules)
// ---------------------------------------------------------------------------
__device__ __half g_bufAh[N_TOT * HID];     // node features (fp16), both towers
__device__ __half g_bufBh[N_TOT * HID];     // xw = x @ W (fp16)
__device__ float g_deg[N_TOT];
__device__ float g_dinv[N_TOT];
__device__ int   g_count[N_TOT];            // counts, then cursor
__device__ int   g_off[N_TOT + 1];          // CSR offsets (by global dst)
__device__ int   g_blocksum[N_SCAN_BLOCKS];
__device__ int   g_srcs[E_TOT];             // global src per sorted edge
__device__ float g_nrm[E_TOT];              // norm per sorted edge
__device__ float g_pooled[2 * G_GRAPHS * HID];
__device__ float g_cnt[2 * G_GRAPHS];
__device__ float g_h[2][G_GRAPHS * OUT_DIM];

// ---------------------------------------------------------------------------
// fp32 -> fp16 conversion of input features (both towers)
// Also zeroes the pool accumulators (independent, saves a launch).
// ---------------------------------------------------------------------------
__global__ void conv_x_kernel(const float* __restrict__ x1,
                              const float* __restrict__ x2) {
    int i = blockIdx.x * blockDim.x + threadIdx.x;   // per 4 elements
    if (i < N_TOT * 32) {
        const float* x = (i < N_NODES * 32) ? x1 : x2;
        int li = (i < N_NODES * 32) ? i : (i - N_NODES * 32);
        float4 v = ((const float4*)x)[li];
        uint2 o;
        *(__half2*)&o.x = __floats2half2_rn(v.x, v.y);
        *(__half2*)&o.y = __floats2half2_rn(v.z, v.w);
        ((uint2*)g_bufAh)[i] = o;
    }
    if (i < 2 * G_GRAPHS * HID) g_pooled[i] = 0.0f;
    if (i < 2 * G_GRAPHS) g_cnt[i] = 0.0f;
}

// ---------------------------------------------------------------------------
// Degree + counts (both edge lists, global node ids)
// ---------------------------------------------------------------------------
__global__ void zero_deg_kernel() {
    int i = blockIdx.x * blockDim.x + threadIdx.x;
    if (i < N_TOT) { g_deg[i] = 0.0f; g_count[i] = 0; }
}

__global__ void deg_count_kernel(const int* __restrict__ ei1,
                                 const float* __restrict__ ea1,
                                 const int* __restrict__ ei2,
                                 const float* __restrict__ ea2) {
    int e = blockIdx.x * blockDim.x + threadIdx.x;
    if (e < E_TOT) {
        int tower = (e >= N_EDGES) ? 1 : 0;
        int le = e - tower * N_EDGES;
        const int* ei = tower ? ei2 : ei1;
        const float* ea = tower ? ea2 : ea1;
        int di = ei[N_EDGES + le] + tower * N_NODES;
        atomicAdd(&g_deg[di], ea[le]);
        atomicAdd(&g_count[di], 1);
    }
}

// ---------------------------------------------------------------------------
// Exclusive scan of g_count -> g_off
// ---------------------------------------------------------------------------
__global__ void __launch_bounds__(SCAN_BLK)
scan_block_kernel() {
    __shared__ int s[SCAN_BLK];
    int i = blockIdx.x * SCAN_BLK + threadIdx.x;
    int v = (i < N_TOT) ? g_count[i] : 0;
    s[threadIdx.x] = v;
    __syncthreads();
    #pragma unroll
    for (int d = 1; d < SCAN_BLK; d <<= 1) {
        int t = (threadIdx.x >= d) ? s[threadIdx.x - d] : 0;
        __syncthreads();
        s[threadIdx.x] += t;
        __syncthreads();
    }
    if (i < N_TOT) g_off[i] = s[threadIdx.x] - v;
    if (threadIdx.x == SCAN_BLK - 1) g_blocksum[blockIdx.x] = s[threadIdx.x];
}

// Parallel top-level scan over 196 block sums (one block, 256 threads)
__global__ void scan_top_kernel() {
    __shared__ int s[256];
    int t = threadIdx.x;
    int v = (t < N_SCAN_BLOCKS) ? g_blocksum[t] : 0;
    s[t] = v;
    __syncthreads();
    #pragma unroll
    for (int d = 1; d < 256; d <<= 1) {
        int tv = (t >= d) ? s[t - d] : 0;
        __syncthreads();
        s[t] += tv;
        __syncthreads();
    }
    if (t < N_SCAN_BLOCKS) g_blocksum[t] = s[t] - v;   // exclusive
    if (t == 255) g_off[N_TOT] = s[255];
}

// also computes dinv (deg is final by now)
__global__ void scan_add_kernel() {
    int i = blockIdx.x * blockDim.x + threadIdx.x;
    if (i < N_TOT) {
        int o = g_off[i] + g_blocksum[i >> 10];
        g_off[i] = o;
        g_count[i] = o;
        g_dinv[i] = rsqrtf(g_deg[i] + 1.0f);
    }
}

__global__ void scatter_kernel(const int* __restrict__ ei1,
                               const float* __restrict__ ea1,
                               const int* __restrict__ ei2,
                               const float* __restrict__ ea2) {
    int e = blockIdx.x * blockDim.x + threadIdx.x;
    if (e < E_TOT) {
        int tower = (e >= N_EDGES) ? 1 : 0;
        int le = e - tower * N_EDGES;
        const int* ei = tower ? ei2 : ei1;
        const float* ea = tower ? ea2 : ea1;
        int si = ei[le] + tower * N_NODES;
        int di = ei[N_EDGES + le] + tower * N_NODES;
        int pos = atomicAdd(&g_count[di], 1);
        g_srcs[pos] = si;
        g_nrm[pos]  = g_dinv[si] * ea[le] * g_dinv[di];
    }
}

// ---------------------------------------------------------------------------
// GEMM (HFMA2, pre-splatted X, fused column halves):
//   bufB[n,c] = sum_k bufA[n,k] * W[k,c]
// Block tile 128(M) x 128(N), 512 threads, 8 rows x 4 cols per thread.
// X in smem splatted: sXd[k*128 + r] (64KB) -- filled ONCE per row block.
// W in smem as uint2 col-quads: sWq[k*32 + q] (32KB) -- one LDS.64 per k.
// fp16 accumulate over chunks of 16 k, promoted to fp32.
// ---------------------------------------------------------------------------
#define GEMM_SMEM_BYTES (HID * 128 * 4 + HID * 32 * 8)   // 64KB + 32KB

__global__ void __launch_bounds__(512, 2)
gemm_kernel(const float* __restrict__ W)
{
    extern __shared__ __half2 smem2[];
    __half2* sXd = smem2;                        // [k*128 + r], splatted
    uint2*   sWq = (uint2*)(smem2 + HID * 128);  // [k*32 + q], 4 cols per entry

    const int tid  = threadIdx.x;
    const int row0 = blockIdx.x * 128;

    // Load W (128 k x 128 cols fp32), convert to half2 col-quads
    {
        const float4* W4 = (const float4*)W;
        #pragma unroll
        for (int i = 0; i < 8; ++i) {
            int idx = tid + i * 512;     // 0..4095 (float4 index)
            int k  = idx >> 5;           // 32 float4 per k-row
            int c4 = idx & 31;           // col quad
            float4 v = W4[idx];
            uint2 o;
            *(__half2*)&o.x = __floats2half2_rn(v.x, v.y);
            *(__half2*)&o.y = __floats2half2_rn(v.z, v.w);
            sWq[k * 32 + c4] = o;
        }
    }

    // Load X tile (128 rows x 128 k fp16), splat each value into sXd[k][r]
    {
        const uint4* Xg = (const uint4*)g_bufAh;   // 8 halfs per uint4
        #pragma unroll
        for (int i = 0; i < 4; ++i) {
            int idx = tid + i * 512;      // 0..2047
            int r   = idx & 127;
            int k8  = idx >> 7;           // 0..15, chunk of 8 k
            int grow = row0 + r;
            uint4 u = make_uint4(0u, 0u, 0u, 0u);
            if (grow < N_TOT) u = Xg[(size_t)grow * 16 + k8];
            const __half* ph = (const __half*)&u;
            #pragma unroll
            for (int t = 0; t < 8; ++t)
                sXd[(k8 * 8 + t) * 128 + r] = __half2half2(ph[t]);
        }
    }
    __syncthreads();

    const int tx = tid & 15;          // col quad within the 64-col half
    const int ty = (tid >> 4) & 15;   // row groups: ty*4 and 64+ty*4
    const int h  = tid >> 8;          // column half 0/1

    float accf[8][4];
    #pragma unroll
    for (int i = 0; i < 8; ++i)
        #pragma unroll
        for (int j = 0; j < 4; ++j) accf[i][j] = 0.0f;

    #pragma unroll
    for (int kc = 0; kc < 8; ++kc) {        // 8 chunks of 16 k
        __half2 acc2[8][2];
        #pragma unroll
        for (int i = 0; i < 8; ++i) {
            acc2[i][0] = __floats2half2_rn(0.0f, 0.0f);
            acc2[i][1] = __floats2half2_rn(0.0f, 0.0f);
        }

        #pragma unroll
        for (int kk = 0; kk < 16; ++kk) {
            int k = kc * 16 + kk;
            uint4 xva = *(const uint4*)&sXd[k * 128 + ty * 4];
            uint4 xvb = *(const uint4*)&sXd[k * 128 + 64 + ty * 4];
            const __half2* pa = (const __half2*)&xva;
            const __half2* pb = (const __half2*)&xvb;

            uint2 wq = sWq[k * 32 + h * 16 + tx];
            __half2 wr0 = *(__half2*)&wq.x;
            __half2 wr1 = *(__half2*)&wq.y;

            #pragma unroll
            for (int i = 0; i < 4; ++i) {
                acc2[i][0] = __hfma2(pa[i], wr0, acc2[i][0]);
                acc2[i][1] = __hfma2(pa[i], wr1, acc2[i][1]);
                acc2[i + 4][0] = __hfma2(pb[i], wr0, acc2[i + 4][0]);
                acc2[i + 4][1] = __hfma2(pb[i], wr1, acc2[i + 4][1]);
            }
        }

        #pragma unroll
        for (int i = 0; i < 8; ++i) {
            float2 f0 = __half22float2(acc2[i][0]);
            float2 f1 = __half22float2(acc2[i][1]);
            accf[i][0] += f0.x; accf[i][1] += f0.y;
            accf[i][2] += f1.x; accf[i][3] += f1.y;
        }
    }

    // Epilogue: fp32 acc -> fp16 global
    const int col0 = h * 64 + tx * 4;
    #pragma unroll
    for (int i = 0; i < 8; ++i) {
        int r = (i < 4) ? (ty * 4 + i) : (64 + ty * 4 + i - 4);
        int grow = row0 + r;
        if (grow < N_TOT) {
            uint2 o;
            *(__half2*)&o.x = __floats2half2_rn(accf[i][0], accf[i][1]);
            *(__half2*)&o.y = __floats2half2_rn(accf[i][2], accf[i][3]);
            *(uint2*)&g_bufBh[(size_t)grow * HID + col0] = o;
        }
    }
}

// ---------------------------------------------------------------------------
// Aggregation: HALF-WARP per destination node (16 lanes x 8 channels).
// (Frozen R10/R12 configuration — 2-edge unroll, separate srcs/nrm arrays.)
// out = act( bias + dinv*dinv * xw[self] + sum_j nrm[j] * xw[src[j]] )
// ---------------------------------------------------------------------------
__device__ __forceinline__ void fma8(float* a, const uint4& v, float n) {
    const __half2* p = (const __half2*)&v;
    float2 q0 = __half22float2(p[0]);
    float2 q1 = __half22float2(p[1]);
    float2 q2 = __half22float2(p[2]);
    float2 q3 = __half22float2(p[3]);
    a[0] += n * q0.x; a[1] += n * q0.y;
    a[2] += n * q1.x; a[3] += n * q1.y;
    a[4] += n * q2.x; a[5] += n * q2.y;
    a[6] += n * q3.x; a[7] += n * q3.y;
}

__global__ void __launch_bounds__(256)
agg_kernel(const float* __restrict__ bias, int act)
{
    int node = (blockIdx.x * blockDim.x + threadIdx.x) >> 4;  // half-warp id
    int ln   = threadIdx.x & 15;
    if (node >= N_TOT) return;

    const uint4* xw = (const uint4*)g_bufBh;

    int beg = g_off[node];
    int end = g_off[node + 1];

    float s = g_dinv[node];
    s = s * s;
    float4 b0 = ((const float4*)bias)[ln * 2];
    float4 b1 = ((const float4*)bias)[ln * 2 + 1];
    float a[8] = { b0.x, b0.y, b0.z, b0.w, b1.x, b1.y, b1.z, b1.w };

    uint4 self = xw[(size_t)node * 16 + ln];
    fma8(a, self, s);

    int j = beg;
    for (; j + 1 < end; j += 2) {
        int   s0 = g_srcs[j];
        int   s1 = g_srcs[j + 1];
        float n0 = g_nrm[j];
        float n1 = g_nrm[j + 1];
        uint4 v0 = xw[(size_t)s0 * 16 + ln];
        uint4 v1 = xw[(size_t)s1 * 16 + ln];
        fma8(a, v0, n0);
        fma8(a, v1, n1);
    }
    if (j < end) {
        int   s0 = g_srcs[j];
        float n0 = g_nrm[j];
        uint4 v0 = xw[(size_t)s0 * 16 + ln];
        fma8(a, v0, n0);
    }

    if (act) {
        #pragma unroll
        for (int i = 0; i < 8; ++i) a[i] = tanhf(a[i]);
    }
    uint4 o;
    *(__half2*)&o.x = __floats2half2_rn(a[0], a[1]);
    *(__half2*)&o.y = __floats2half2_rn(a[2], a[3]);
    *(__half2*)&o.z = __floats2half2_rn(a[4], a[5]);
    *(__half2*)&o.w = __floats2half2_rn(a[6], a[7]);
    ((uint4*)g_bufAh)[(size_t)node * 16 + ln] = o;
}

// ---------------------------------------------------------------------------
// Global mean pool (batch sorted per tower). grid = 2 * POOL_BLOCKS_T.
// ---------------------------------------------------------------------------
#define POOL_CHUNK 128
#define POOL_BLOCKS_T ((N_NODES + POOL_CHUNK - 1) / POOL_CHUNK)

__global__ void pool_kernel(const int* __restrict__ batch1,
                            const int* __restrict__ batch2) {
    int tower = (blockIdx.x >= POOL_BLOCKS_T) ? 1 : 0;
    const int* batch = tower ? batch2 : batch1;
    int blk = blockIdx.x - tower * POOL_BLOCKS_T;
    int c  = threadIdx.x;
    int n0 = blk * POOL_CHUNK;
    int n1 = n0 + POOL_CHUNK;
    if (n1 > N_NODES) n1 = N_NODES;
    if (n0 >= N_NODES) return;

    int gbase = tower * G_GRAPHS;
    size_t nodeoff = (size_t)tower * N_NODES;

    float acc = 0.0f;
    int cur = batch[n0];
    int run = 0;
    for (int n = n0; n < n1; ++n) {
        int g = batch[n];
        if (g != cur) {
            atomicAdd(&g_pooled[(gbase + cur) * HID + c], acc);
            if (c == 0) atomicAdd(&g_cnt[gbase + cur], (float)run);
            acc = 0.0f; run = 0; cur = g;
        }
        acc += __half2float(g_bufAh[(nodeoff + n) * HID + c]);
        run++;
    }
    atomicAdd(&g_pooled[(gbase + cur) * HID + c], acc);
    if (c == 0) atomicAdd(&g_cnt[gbase + cur], (float)run);
}

// ---------------------------------------------------------------------------
// MLP head: fc1 (128->64, relu) + 5 x fc (64->64, relu). grid = 2 (towers).
// ---------------------------------------------------------------------------
__global__ void __launch_bounds__(512)
mlp_kernel(const float* __restrict__ fcW1, const float* __restrict__ fcb1,
           const float* __restrict__ fcW,  const float* __restrict__ fcb)
{
    __shared__ float ha[G_GRAPHS * OUT_DIM];
    __shared__ float hb[G_GRAPHS * OUT_DIM];
    int t = threadIdx.x;
    int tower = blockIdx.x;
    int gbase = tower * G_GRAPHS;

    for (int idx = t; idx < G_GRAPHS * OUT_DIM; idx += 512) {
        int g = idx >> 6, o = idx & 63;
        float ic = g_cnt[gbase + g];
        ic = 1.0f / fmaxf(ic, 1.0f);
        float s = fcb1[o];
        #pragma unroll 4
        for (int k = 0; k < HID; ++k)
            s += g_pooled[(gbase + g) * HID + k] * ic * fcW1[k * OUT_DIM + o];
        ha[idx] = fmaxf(s, 0.0f);
    }
    __syncthreads();

    float* srcb = ha;
    float* dstb = hb;
    for (int L = 0; L < 5; ++L) {
        const float* Wp = fcW + L * OUT_DIM * OUT_DIM;
        const float* bp = fcb + L * OUT_DIM;
        for (int idx = t; idx < G_GRAPHS * OUT_DIM; idx += 512) {
            int g = idx >> 6, o = idx & 63;
            float s = bp[o];
            #pragma unroll 8
            for (int k = 0; k < OUT_DIM; ++k)
                s += srcb[g * OUT_DIM + k] * Wp[k * OUT_DIM + o];
            dstb[idx] = fmaxf(s, 0.0f);
        }
        __syncthreads();
        float* tmp = srcb; srcb = dstb; dstb = tmp;
    }

    for (int idx = t; idx < G_GRAPHS * OUT_DIM; idx += 512)
        g_h[tower][idx] = srcb[idx];
}

__global__ void final_kernel(float* __restrict__ out) {
    int g = threadIdx.x;
    if (g < G_GRAPHS) {
        float s = 0.0f;
        #pragma unroll 8
        for (int k = 0; k < OUT_DIM; ++k) {
            float d = g_h[0][g * OUT_DIM + k] - g_h[1][g * OUT_DIM + k];
            s += d * d;
        }
        out[g] = sqrtf(s);
    }
}

// ---------------------------------------------------------------------------
// Host launcher
// ---------------------------------------------------------------------------
extern "C" void kernel_launch(void* const* d_in, const int* in_sizes, int n_in,
                              void* d_out, int out_size)
{
    const float* x1  = (const float*)d_in[0];
    const int*   ei1 = (const int*)  d_in[1];
    const float* ea1 = (const float*)d_in[2];
    const int*   bt1 = (const int*)  d_in[3];
    const float* x2  = (const float*)d_in[4];
    const int*   ei2 = (const int*)  d_in[5];
    const float* ea2 = (const float*)d_in[6];
    const int*   bt2 = (const int*)  d_in[7];
    const float* convW = (const float*)d_in[8];
    const float* convB = (const float*)d_in[9];
    const float* fcW1  = (const float*)d_in[10];
    const float* fcb1  = (const float*)d_in[11];
    const float* fcW   = (const float*)d_in[12];
    const float* fcb   = (const float*)d_in[13];

    const bool ACTS[6] = { true, true, false, true, true, true };

    cudaFuncSetAttribute(gemm_kernel,
                         cudaFuncAttributeMaxDynamicSharedMemorySize,
                         GEMM_SMEM_BYTES);

    const int NBN = (N_TOT + 255) / 256;
    const int NBE = (E_TOT + 255) / 256;
    const int GEMM_BLOCKS = (N_TOT + 127) / 128;
    const int AGG_BLOCKS = (N_TOT * 16) / 256;

    // Build unified dst-sorted CSR + norms (once; reused for 6 layers)
    zero_deg_kernel<<<NBN, 256>>>();
    deg_count_kernel<<<NBE, 256>>>(ei1, ea1, ei2, ea2);
    scan_block_kernel<<<N_SCAN_BLOCKS, SCAN_BLK>>>();
    scan_top_kernel<<<1, 256>>>();
    scan_add_kernel<<<NBN, 256>>>();
    scatter_kernel<<<NBE, 256>>>(ei1, ea1, ei2, ea2);

    // x -> fp16 (both towers) + pool accumulator zeroing
    conv_x_kernel<<<(N_TOT * 32 + 255) / 256, 256>>>(x1, x2);

    for (int L = 0; L < 6; ++L) {
        gemm_kernel<<<GEMM_BLOCKS, 512, GEMM_SMEM_BYTES>>>(
            convW + (size_t)L * HID * HID);
        agg_kernel<<<AGG_BLOCKS, 256>>>(convB + L * HID, ACTS[L] ? 1 : 0);
    }

    pool_kernel<<<2 * POOL_BLOCKS_T, 128>>>(bt1, bt2);
    mlp_kernel<<<2, 512>>>(fcW1, fcb1, fcW, fcb);

    final_kernel<<<1, 64>>>((float*)d_out);
}

// round 15
// speedup vs baseline: 1.6749x; 1.0228x over previous
#include <cuda_runtime.h>
#include <cuda_fp16.h>
#include <math.h>

// Problem constants (fixed by the dataset)
#define N_NODES 100000
#define N_TOT   200000            // both towers fused
#define N_EDGES 1600000
#define E_TOT   3200000
#define G_GRAPHS 64
#define HID 128
#define OUT_DIM 64

#define SCAN_BLK 1024
#define N_SCAN_BLOCKS ((N_TOT + SCAN_BLK - 1) / SCAN_BLK)   // 196

// ---------------------------------------------------------------------------
// Scratch (device globals; allocation-free per harness rules)
// ---------------------------------------------------------------------------
__device__ __half g_bufAh[N_TOT * HID];     // node features (fp16), both towers
__device__ __half g_bufBh[N_TOT * HID];     // xw = x @ W (fp16)
__device__ float g_deg[N_TOT];
__device__ float g_dinv[N_TOT];
__device__ int   g_count[N_TOT];            // counts, then cursor
__device__ int   g_off[N_TOT + 1];          // CSR offsets (by global dst)
__device__ int   g_blocksum[N_SCAN_BLOCKS];
__device__ int   g_srcs[E_TOT];             // global src per sorted edge
__device__ float g_nrm[E_TOT];              // norm per sorted edge
__device__ float g_pooled[2 * G_GRAPHS * HID];
__device__ float g_cnt[2 * G_GRAPHS];
__device__ float g_h[2][G_GRAPHS * OUT_DIM];

// ---------------------------------------------------------------------------
// fp32 -> fp16 conversion of input features (both towers)
// Also zeroes the pool accumulators (independent, saves a launch).
// ---------------------------------------------------------------------------
__global__ void conv_x_kernel(const float* __restrict__ x1,
                              const float* __restrict__ x2) {
    int i = blockIdx.x * blockDim.x + threadIdx.x;   // per 4 elements
    if (i < N_TOT * 32) {
        const float* x = (i < N_NODES * 32) ? x1 : x2;
        int li = (i < N_NODES * 32) ? i : (i - N_NODES * 32);
        float4 v = ((const float4*)x)[li];
        uint2 o;
        *(__half2*)&o.x = __floats2half2_rn(v.x, v.y);
        *(__half2*)&o.y = __floats2half2_rn(v.z, v.w);
        ((uint2*)g_bufAh)[i] = o;
    }
    if (i < 2 * G_GRAPHS * HID) g_pooled[i] = 0.0f;
    if (i < 2 * G_GRAPHS) g_cnt[i] = 0.0f;
}

// ---------------------------------------------------------------------------
// Degree + counts (both edge lists, global node ids)
// ---------------------------------------------------------------------------
__global__ void zero_deg_kernel() {
    int i = blockIdx.x * blockDim.x + threadIdx.x;
    if (i < N_TOT) { g_deg[i] = 0.0f; g_count[i] = 0; }
}

__global__ void deg_count_kernel(const int* __restrict__ ei1,
                                 const float* __restrict__ ea1,
                                 const int* __restrict__ ei2,
                                 const float* __restrict__ ea2) {
    int e = blockIdx.x * blockDim.x + threadIdx.x;
    if (e < E_TOT) {
        int tower = (e >= N_EDGES) ? 1 : 0;
        int le = e - tower * N_EDGES;
        const int* ei = tower ? ei2 : ei1;
        const float* ea = tower ? ea2 : ea1;
        int di = ei[N_EDGES + le] + tower * N_NODES;
        atomicAdd(&g_deg[di], ea[le]);
        atomicAdd(&g_count[di], 1);
    }
}

// ---------------------------------------------------------------------------
// Exclusive scan of g_count -> g_off
// ---------------------------------------------------------------------------
__global__ void __launch_bounds__(SCAN_BLK)
scan_block_kernel() {
    __shared__ int s[SCAN_BLK];
    int i = blockIdx.x * SCAN_BLK + threadIdx.x;
    int v = (i < N_TOT) ? g_count[i] : 0;
    s[threadIdx.x] = v;
    __syncthreads();
    #pragma unroll
    for (int d = 1; d < SCAN_BLK; d <<= 1) {
        int t = (threadIdx.x >= d) ? s[threadIdx.x - d] : 0;
        __syncthreads();
        s[threadIdx.x] += t;
        __syncthreads();
    }
    if (i < N_TOT) g_off[i] = s[threadIdx.x] - v;
    if (threadIdx.x == SCAN_BLK - 1) g_blocksum[blockIdx.x] = s[threadIdx.x];
}

// Parallel top-level scan over 196 block sums (one block, 256 threads)
__global__ void scan_top_kernel() {
    __shared__ int s[256];
    int t = threadIdx.x;
    int v = (t < N_SCAN_BLOCKS) ? g_blocksum[t] : 0;
    s[t] = v;
    __syncthreads();
    #pragma unroll
    for (int d = 1; d < 256; d <<= 1) {
        int tv = (t >= d) ? s[t - d] : 0;
        __syncthreads();
        s[t] += tv;
        __syncthreads();
    }
    if (t < N_SCAN_BLOCKS) g_blocksum[t] = s[t] - v;   // exclusive
    if (t == 255) g_off[N_TOT] = s[255];
}

// also computes dinv (deg is final by now)
__global__ void scan_add_kernel() {
    int i = blockIdx.x * blockDim.x + threadIdx.x;
    if (i < N_TOT) {
        int o = g_off[i] + g_blocksum[i >> 10];
        g_off[i] = o;
        g_count[i] = o;
        g_dinv[i] = rsqrtf(g_deg[i] + 1.0f);
    }
}

__global__ void scatter_kernel(const int* __restrict__ ei1,
                               const float* __restrict__ ea1,
                               const int* __restrict__ ei2,
                               const float* __restrict__ ea2) {
    int e = blockIdx.x * blockDim.x + threadIdx.x;
    if (e < E_TOT) {
        int tower = (e >= N_EDGES) ? 1 : 0;
        int le = e - tower * N_EDGES;
        const int* ei = tower ? ei2 : ei1;
        const float* ea = tower ? ea2 : ea1;
        int si = ei[le] + tower * N_NODES;
        int di = ei[N_EDGES + le] + tower * N_NODES;
        int pos = atomicAdd(&g_count[di], 1);
        g_srcs[pos] = si;
        g_nrm[pos]  = g_dinv[si] * ea[le] * g_dinv[di];
    }
}

// ---------------------------------------------------------------------------
// GEMM (HFMA2, pre-splatted X, fused column halves):
//   bufB[n,c] = sum_k bufA[n,k] * W[k,c]
// Block tile 128(M) x 128(N), 512 threads, 8 rows x 4 cols per thread.
// X in smem splatted: sXd[k*128 + r] (64KB) -- filled ONCE per row block.
// W in smem as uint2 col-quads: sWq[k*32 + q] (32KB) -- one LDS.64 per k.
// fp16 accumulate over chunks of 16 k, promoted to fp32.
// ---------------------------------------------------------------------------
#define GEMM_SMEM_BYTES (HID * 128 * 4 + HID * 32 * 8)   // 64KB + 32KB

__global__ void __launch_bounds__(512, 2)
gemm_kernel(const float* __restrict__ W)
{
    extern __shared__ __half2 smem2[];
    __half2* sXd = smem2;                        // [k*128 + r], splatted
    uint2*   sWq = (uint2*)(smem2 + HID * 128);  // [k*32 + q], 4 cols per entry

    const int tid  = threadIdx.x;
    const int row0 = blockIdx.x * 128;

    // Load W (128 k x 128 cols fp32), convert to half2 col-quads
    {
        const float4* W4 = (const float4*)W;
        #pragma unroll
        for (int i = 0; i < 8; ++i) {
            int idx = tid + i * 512;     // 0..4095 (float4 index)
            int k  = idx >> 5;           // 32 float4 per k-row
            int c4 = idx & 31;           // col quad
            float4 v = W4[idx];
            uint2 o;
            *(__half2*)&o.x = __floats2half2_rn(v.x, v.y);
            *(__half2*)&o.y = __floats2half2_rn(v.z, v.w);
            sWq[k * 32 + c4] = o;
        }
    }

    // Load X tile (128 rows x 128 k fp16), splat each value into sXd[k][r]
    {
        const uint4* Xg = (const uint4*)g_bufAh;   // 8 halfs per uint4
        #pragma unroll
        for (int i = 0; i < 4; ++i) {
            int idx = tid + i * 512;      // 0..2047
            int r   = idx & 127;
            int k8  = idx >> 7;           // 0..15, chunk of 8 k
            int grow = row0 + r;
            uint4 u = make_uint4(0u, 0u, 0u, 0u);
            if (grow < N_TOT) u = Xg[(size_t)grow * 16 + k8];
            const __half* ph = (const __half*)&u;
            #pragma unroll
            for (int t = 0; t < 8; ++t)
                sXd[(k8 * 8 + t) * 128 + r] = __half2half2(ph[t]);
        }
    }
    __syncthreads();

    const int tx = tid & 15;          // col quad within the 64-col half
    const int ty = (tid >> 4) & 15;   // row groups: ty*4 and 64+ty*4
    const int h  = tid >> 8;          // column half 0/1

    float accf[8][4];
    #pragma unroll
    for (int i = 0; i < 8; ++i)
        #pragma unroll
        for (int j = 0; j < 4; ++j) accf[i][j] = 0.0f;

    #pragma unroll
    for (int kc = 0; kc < 8; ++kc) {        // 8 chunks of 16 k
        __half2 acc2[8][2];
        #pragma unroll
        for (int i = 0; i < 8; ++i) {
            acc2[i][0] = __floats2half2_rn(0.0f, 0.0f);
            acc2[i][1] = __floats2half2_rn(0.0f, 0.0f);
        }

        #pragma unroll
        for (int kk = 0; kk < 16; ++kk) {
            int k = kc * 16 + kk;
            uint4 xva = *(const uint4*)&sXd[k * 128 + ty * 4];
            uint4 xvb = *(const uint4*)&sXd[k * 128 + 64 + ty * 4];
            const __half2* pa = (const __half2*)&xva;
            const __half2* pb = (const __half2*)&xvb;

            uint2 wq = sWq[k * 32 + h * 16 + tx];
            __half2 wr0 = *(__half2*)&wq.x;
            __half2 wr1 = *(__half2*)&wq.y;

            #pragma unroll
            for (int i = 0; i < 4; ++i) {
                acc2[i][0] = __hfma2(pa[i], wr0, acc2[i][0]);
                acc2[i][1] = __hfma2(pa[i], wr1, acc2[i][1]);
                acc2[i + 4][0] = __hfma2(pb[i], wr0, acc2[i + 4][0]);
                acc2[i + 4][1] = __hfma2(pb[i], wr1, acc2[i + 4][1]);
            }
        }

        #pragma unroll
        for (int i = 0; i < 8; ++i) {
            float2 f0 = __half22float2(acc2[i][0]);
            float2 f1 = __half22float2(acc2[i][1]);
            accf[i][0] += f0.x; accf[i][1] += f0.y;
            accf[i][2] += f1.x; accf[i][3] += f1.y;
        }
    }

    // Epilogue: fp32 acc -> fp16 global
    const int col0 = h * 64 + tx * 4;
    #pragma unroll
    for (int i = 0; i < 8; ++i) {
        int r = (i < 4) ? (ty * 4 + i) : (64 + ty * 4 + i - 4);
        int grow = row0 + r;
        if (grow < N_TOT) {
            uint2 o;
            *(__half2*)&o.x = __floats2half2_rn(accf[i][0], accf[i][1]);
            *(__half2*)&o.y = __floats2half2_rn(accf[i][2], accf[i][3]);
            *(uint2*)&g_bufBh[(size_t)grow * HID + col0] = o;
        }
    }
}

// ---------------------------------------------------------------------------
// Aggregation: HALF-WARP per destination node (16 lanes x 8 channels).
// Frozen R10/R12 loop; activation now uses the HW tanh approximation
// (__tanhf -> MUFU.TANH, single instruction, ~2e-4 rel accuracy).
// out = act( bias + dinv*dinv * xw[self] + sum_j nrm[j] * xw[src[j]] )
// ---------------------------------------------------------------------------
__device__ __forceinline__ void fma8(float* a, const uint4& v, float n) {
    const __half2* p = (const __half2*)&v;
    float2 q0 = __half22float2(p[0]);
    float2 q1 = __half22float2(p[1]);
    float2 q2 = __half22float2(p[2]);
    float2 q3 = __half22float2(p[3]);
    a[0] += n * q0.x; a[1] += n * q0.y;
    a[2] += n * q1.x; a[3] += n * q1.y;
    a[4] += n * q2.x; a[5] += n * q2.y;
    a[6] += n * q3.x; a[7] += n * q3.y;
}

__global__ void __launch_bounds__(256)
agg_kernel(const float* __restrict__ bias, int act)
{
    int node = (blockIdx.x * blockDim.x + threadIdx.x) >> 4;  // half-warp id
    int ln   = threadIdx.x & 15;
    if (node >= N_TOT) return;

    const uint4* xw = (const uint4*)g_bufBh;

    int beg = g_off[node];
    int end = g_off[node + 1];

    float s = g_dinv[node];
    s = s * s;
    float4 b0 = ((const float4*)bias)[ln * 2];
    float4 b1 = ((const float4*)bias)[ln * 2 + 1];
    float a[8] = { b0.x, b0.y, b0.z, b0.w, b1.x, b1.y, b1.z, b1.w };

    uint4 self = xw[(size_t)node * 16 + ln];
    fma8(a, self, s);

    int j = beg;
    for (; j + 1 < end; j += 2) {
        int   s0 = g_srcs[j];
        int   s1 = g_srcs[j + 1];
        float n0 = g_nrm[j];
        float n1 = g_nrm[j + 1];
        uint4 v0 = xw[(size_t)s0 * 16 + ln];
        uint4 v1 = xw[(size_t)s1 * 16 + ln];
        fma8(a, v0, n0);
        fma8(a, v1, n1);
    }
    if (j < end) {
        int   s0 = g_srcs[j];
        float n0 = g_nrm[j];
        uint4 v0 = xw[(size_t)s0 * 16 + ln];
        fma8(a, v0, n0);
    }

    if (act) {
        #pragma unroll
        for (int i = 0; i < 8; ++i) a[i] = __tanhf(a[i]);
    }
    uint4 o;
    *(__half2*)&o.x = __floats2half2_rn(a[0], a[1]);
    *(__half2*)&o.y = __floats2half2_rn(a[2], a[3]);
    *(__half2*)&o.z = __floats2half2_rn(a[4], a[5]);
    *(__half2*)&o.w = __floats2half2_rn(a[6], a[7]);
    ((uint4*)g_bufAh)[(size_t)node * 16 + ln] = o;
}

// ---------------------------------------------------------------------------
// Global mean pool (batch sorted per tower). grid = 2 * POOL_BLOCKS_T.
// ---------------------------------------------------------------------------
#define POOL_CHUNK 128
#define POOL_BLOCKS_T ((N_NODES + POOL_CHUNK - 1) / POOL_CHUNK)

__global__ void pool_kernel(const int* __restrict__ batch1,
                            const int* __restrict__ batch2) {
    int tower = (blockIdx.x >= POOL_BLOCKS_T) ? 1 : 0;
    const int* batch = tower ? batch2 : batch1;
    int blk = blockIdx.x - tower * POOL_BLOCKS_T;
    int c  = threadIdx.x;
    int n0 = blk * POOL_CHUNK;
    int n1 = n0 + POOL_CHUNK;
    if (n1 > N_NODES) n1 = N_NODES;
    if (n0 >= N_NODES) return;

    int gbase = tower * G_GRAPHS;
    size_t nodeoff = (size_t)tower * N_NODES;

    float acc = 0.0f;
    int cur = batch[n0];
    int run = 0;
    for (int n = n0; n < n1; ++n) {
        int g = batch[n];
        if (g != cur) {
            atomicAdd(&g_pooled[(gbase + cur) * HID + c], acc);
            if (c == 0) atomicAdd(&g_cnt[gbase + cur], (float)run);
            acc = 0.0f; run = 0; cur = g;
        }
        acc += __half2float(g_bufAh[(nodeoff + n) * HID + c]);
        run++;
    }
    atomicAdd(&g_pooled[(gbase + cur) * HID + c], acc);
    if (c == 0) atomicAdd(&g_cnt[gbase + cur], (float)run);
}

// ---------------------------------------------------------------------------
// MLP head: fc1 (128->64, relu) + 5 x fc (64->64, relu). grid = 2 (towers).
// ---------------------------------------------------------------------------
__global__ void __launch_bounds__(512)
mlp_kernel(const float* __restrict__ fcW1, const float* __restrict__ fcb1,
           const float* __restrict__ fcW,  const float* __restrict__ fcb)
{
    __shared__ float ha[G_GRAPHS * OUT_DIM];
    __shared__ float hb[G_GRAPHS * OUT_DIM];
    int t = threadIdx.x;
    int tower = blockIdx.x;
    int gbase = tower * G_GRAPHS;

    for (int idx = t; idx < G_GRAPHS * OUT_DIM; idx += 512) {
        int g = idx >> 6, o = idx & 63;
        float ic = g_cnt[gbase + g];
        ic = 1.0f / fmaxf(ic, 1.0f);
        float s = fcb1[o];
        #pragma unroll 4
        for (int k = 0; k < HID; ++k)
            s += g_pooled[(gbase + g) * HID + k] * ic * fcW1[k * OUT_DIM + o];
        ha[idx] = fmaxf(s, 0.0f);
    }
    __syncthreads();

    float* srcb = ha;
    float* dstb = hb;
    for (int L = 0; L < 5; ++L) {
        const float* Wp = fcW + L * OUT_DIM * OUT_DIM;
        const float* bp = fcb + L * OUT_DIM;
        for (int idx = t; idx < G_GRAPHS * OUT_DIM; idx += 512) {
            int g = idx >> 6, o = idx & 63;
            float s = bp[o];
            #pragma unroll 8
            for (int k = 0; k < OUT_DIM; ++k)
                s += srcb[g * OUT_DIM + k] * Wp[k * OUT_DIM + o];
            dstb[idx] = fmaxf(s, 0.0f);
        }
        __syncthreads();
        float* tmp = srcb; srcb = dstb; dstb = tmp;
    }

    for (int idx = t; idx < G_GRAPHS * OUT_DIM; idx += 512)
        g_h[tower][idx] = srcb[idx];
}

__global__ void final_kernel(float* __restrict__ out) {
    int g = threadIdx.x;
    if (g < G_GRAPHS) {
        float s = 0.0f;
        #pragma unroll 8
        for (int k = 0; k < OUT_DIM; ++k) {
            float d = g_h[0][g * OUT_DIM + k] - g_h[1][g * OUT_DIM + k];
            s += d * d;
        }
        out[g] = sqrtf(s);
    }
}

// ---------------------------------------------------------------------------
// Host launcher
// ---------------------------------------------------------------------------
extern "C" void kernel_launch(void* const* d_in, const int* in_sizes, int n_in,
                              void* d_out, int out_size)
{
    const float* x1  = (const float*)d_in[0];
    const int*   ei1 = (const int*)  d_in[1];
    const float* ea1 = (const float*)d_in[2];
    const int*   bt1 = (const int*)  d_in[3];
    const float* x2  = (const float*)d_in[4];
    const int*   ei2 = (const int*)  d_in[5];
    const float* ea2 = (const float*)d_in[6];
    const int*   bt2 = (const int*)  d_in[7];
    const float* convW = (const float*)d_in[8];
    const float* convB = (const float*)d_in[9];
    const float* fcW1  = (const float*)d_in[10];
    const float* fcb1  = (const float*)d_in[11];
    const float* fcW   = (const float*)d_in[12];
    const float* fcb   = (const float*)d_in[13];

    const bool ACTS[6] = { true, true, false, true, true, true };

    cudaFuncSetAttribute(gemm_kernel,
                         cudaFuncAttributeMaxDynamicSharedMemorySize,
                         GEMM_SMEM_BYTES);

    const int NBN = (N_TOT + 255) / 256;
    const int NBE = (E_TOT + 255) / 256;
    const int GEMM_BLOCKS = (N_TOT + 127) / 128;
    const int AGG_BLOCKS = (N_TOT * 16) / 256;

    // Build unified dst-sorted CSR + norms (once; reused for 6 layers)
    zero_deg_kernel<<<NBN, 256>>>();
    deg_count_kernel<<<NBE, 256>>>(ei1, ea1, ei2, ea2);
    scan_block_kernel<<<N_SCAN_BLOCKS, SCAN_BLK>>>();
    scan_top_kernel<<<1, 256>>>();
    scan_add_kernel<<<NBN, 256>>>();
    scatter_kernel<<<NBE, 256>>>(ei1, ea1, ei2, ea2);

    // x -> fp16 (both towers) + pool accumulator zeroing
    conv_x_kernel<<<(N_TOT * 32 + 255) / 256, 256>>>(x1, x2);

    for (int L = 0; L < 6; ++L) {
        gemm_kernel<<<GEMM_BLOCKS, 512, GEMM_SMEM_BYTES>>>(
            convW + (size_t)L * HID * HID);
        agg_kernel<<<AGG_BLOCKS, 256>>>(convB + L * HID, ACTS[L] ? 1 : 0);
    }

    pool_kernel<<<2 * POOL_BLOCKS_T, 128>>>(bt1, bt2);
    mlp_kernel<<<2, 512>>>(fcW1, fcb1, fcW, fcb);

    final_kernel<<<1, 64>>>((float*)d_out);
}

// round 16
// speedup vs baseline: 1.7287x; 1.0321x over previous
#include <cuda_runtime.h>
#include <cuda_fp16.h>
#include <math.h>

// Problem constants (fixed by the dataset)
#define N_NODES 100000
#define N_TOT   200000            // both towers fused
#define N_EDGES 1600000
#define E_TOT   3200000
#define G_GRAPHS 64
#define HID 128
#define OUT_DIM 64

#define SCAN_BLK 1024
#define N_SCAN_BLOCKS ((N_TOT + SCAN_BLK - 1) / SCAN_BLK)   // 196

// ---------------------------------------------------------------------------
// Scratch (device globals; allocation-free per harness rules)
// ---------------------------------------------------------------------------
__device__ __half g_bufAh[N_TOT * HID];     // node features (fp16), both towers
__device__ __half g_bufBh[N_TOT * HID];     // xw = x @ W (fp16)
__device__ float g_deg[N_TOT];
__device__ float g_dinv[N_TOT];
__device__ int   g_count[N_TOT];            // counts, then cursor
__device__ int   g_off[N_TOT + 1];          // CSR offsets (by global dst)
__device__ int   g_blocksum[N_SCAN_BLOCKS];
__device__ int   g_srcs[E_TOT];             // global src per sorted edge
__device__ float g_nrm[E_TOT];              // norm per sorted edge
__device__ float g_pooled[2 * G_GRAPHS * HID];
__device__ float g_cnt[2 * G_GRAPHS];
__device__ float g_h[2][G_GRAPHS * OUT_DIM];

// ---------------------------------------------------------------------------
// fp32 -> fp16 conversion of input features (both towers)
// Also zeroes the pool accumulators (independent, saves a launch).
// ---------------------------------------------------------------------------
__global__ void conv_x_kernel(const float* __restrict__ x1,
                              const float* __restrict__ x2) {
    int i = blockIdx.x * blockDim.x + threadIdx.x;   // per 4 elements
    if (i < N_TOT * 32) {
        const float* x = (i < N_NODES * 32) ? x1 : x2;
        int li = (i < N_NODES * 32) ? i : (i - N_NODES * 32);
        float4 v = ((const float4*)x)[li];
        uint2 o;
        *(__half2*)&o.x = __floats2half2_rn(v.x, v.y);
        *(__half2*)&o.y = __floats2half2_rn(v.z, v.w);
        ((uint2*)g_bufAh)[i] = o;
    }
    if (i < 2 * G_GRAPHS * HID) g_pooled[i] = 0.0f;
    if (i < 2 * G_GRAPHS) g_cnt[i] = 0.0f;
}

// ---------------------------------------------------------------------------
// Degree + counts (both edge lists, global node ids)
// ---------------------------------------------------------------------------
__global__ void zero_deg_kernel() {
    int i = blockIdx.x * blockDim.x + threadIdx.x;
    if (i < N_TOT) { g_deg[i] = 0.0f; g_count[i] = 0; }
}

__global__ void deg_count_kernel(const int* __restrict__ ei1,
                                 const float* __restrict__ ea1,
                                 const int* __restrict__ ei2,
                                 const float* __restrict__ ea2) {
    int e = blockIdx.x * blockDim.x + threadIdx.x;
    if (e < E_TOT) {
        int tower = (e >= N_EDGES) ? 1 : 0;
        int le = e - tower * N_EDGES;
        const int* ei = tower ? ei2 : ei1;
        const float* ea = tower ? ea2 : ea1;
        int di = ei[N_EDGES + le] + tower * N_NODES;
        atomicAdd(&g_deg[di], ea[le]);
        atomicAdd(&g_count[di], 1);
    }
}

// ---------------------------------------------------------------------------
// Exclusive scan of g_count -> g_off
// ---------------------------------------------------------------------------
__global__ void __launch_bounds__(SCAN_BLK)
scan_block_kernel() {
    __shared__ int s[SCAN_BLK];
    int i = blockIdx.x * SCAN_BLK + threadIdx.x;
    int v = (i < N_TOT) ? g_count[i] : 0;
    s[threadIdx.x] = v;
    __syncthreads();
    #pragma unroll
    for (int d = 1; d < SCAN_BLK; d <<= 1) {
        int t = (threadIdx.x >= d) ? s[threadIdx.x - d] : 0;
        __syncthreads();
        s[threadIdx.x] += t;
        __syncthreads();
    }
    if (i < N_TOT) g_off[i] = s[threadIdx.x] - v;
    if (threadIdx.x == SCAN_BLK - 1) g_blocksum[blockIdx.x] = s[threadIdx.x];
}

// Parallel top-level scan over 196 block sums (one block, 256 threads)
__global__ void scan_top_kernel() {
    __shared__ int s[256];
    int t = threadIdx.x;
    int v = (t < N_SCAN_BLOCKS) ? g_blocksum[t] : 0;
    s[t] = v;
    __syncthreads();
    #pragma unroll
    for (int d = 1; d < 256; d <<= 1) {
        int tv = (t >= d) ? s[t - d] : 0;
        __syncthreads();
        s[t] += tv;
        __syncthreads();
    }
    if (t < N_SCAN_BLOCKS) g_blocksum[t] = s[t] - v;   // exclusive
    if (t == 255) g_off[N_TOT] = s[255];
}

// also computes dinv (deg is final by now)
__global__ void scan_add_kernel() {
    int i = blockIdx.x * blockDim.x + threadIdx.x;
    if (i < N_TOT) {
        int o = g_off[i] + g_blocksum[i >> 10];
        g_off[i] = o;
        g_count[i] = o;
        g_dinv[i] = rsqrtf(g_deg[i] + 1.0f);
    }
}

__global__ void scatter_kernel(const int* __restrict__ ei1,
                               const float* __restrict__ ea1,
                               const int* __restrict__ ei2,
                               const float* __restrict__ ea2) {
    int e = blockIdx.x * blockDim.x + threadIdx.x;
    if (e < E_TOT) {
        int tower = (e >= N_EDGES) ? 1 : 0;
        int le = e - tower * N_EDGES;
        const int* ei = tower ? ei2 : ei1;
        const float* ea = tower ? ea2 : ea1;
        int si = ei[le] + tower * N_NODES;
        int di = ei[N_EDGES + le] + tower * N_NODES;
        int pos = atomicAdd(&g_count[di], 1);
        g_srcs[pos] = si;
        g_nrm[pos]  = g_dinv[si] * ea[le] * g_dinv[di];
    }
}

// ---------------------------------------------------------------------------
// GEMM (HFMA2, pre-splatted X, fused column halves):
//   bufB[n,c] = sum_k bufA[n,k] * W[k,c]
// Block tile 128(M) x 128(N), 512 threads, 8 rows x 4 cols per thread.
// X in smem splatted: sXd[k*128 + r] (64KB) -- filled ONCE per row block.
// W in smem as uint2 col-quads: sWq[k*32 + q] (32KB) -- one LDS.64 per k.
// fp16 accumulate over chunks of 32 k, promoted to fp32 (4 promotions).
// ---------------------------------------------------------------------------
#define GEMM_SMEM_BYTES (HID * 128 * 4 + HID * 32 * 8)   // 64KB + 32KB

__global__ void __launch_bounds__(512, 2)
gemm_kernel(const float* __restrict__ W)
{
    extern __shared__ __half2 smem2[];
    __half2* sXd = smem2;                        // [k*128 + r], splatted
    uint2*   sWq = (uint2*)(smem2 + HID * 128);  // [k*32 + q], 4 cols per entry

    const int tid  = threadIdx.x;
    const int row0 = blockIdx.x * 128;

    // Load W (128 k x 128 cols fp32), convert to half2 col-quads
    {
        const float4* W4 = (const float4*)W;
        #pragma unroll
        for (int i = 0; i < 8; ++i) {
            int idx = tid + i * 512;     // 0..4095 (float4 index)
            int k  = idx >> 5;           // 32 float4 per k-row
            int c4 = idx & 31;           // col quad
            float4 v = W4[idx];
            uint2 o;
            *(__half2*)&o.x = __floats2half2_rn(v.x, v.y);
            *(__half2*)&o.y = __floats2half2_rn(v.z, v.w);
            sWq[k * 32 + c4] = o;
        }
    }

    // Load X tile (128 rows x 128 k fp16), splat each value into sXd[k][r]
    {
        const uint4* Xg = (const uint4*)g_bufAh;   // 8 halfs per uint4
        #pragma unroll
        for (int i = 0; i < 4; ++i) {
            int idx = tid + i * 512;      // 0..2047
            int r   = idx & 127;
            int k8  = idx >> 7;           // 0..15, chunk of 8 k
            int grow = row0 + r;
            uint4 u = make_uint4(0u, 0u, 0u, 0u);
            if (grow < N_TOT) u = Xg[(size_t)grow * 16 + k8];
            const __half* ph = (const __half*)&u;
            #pragma unroll
            for (int t = 0; t < 8; ++t)
                sXd[(k8 * 8 + t) * 128 + r] = __half2half2(ph[t]);
        }
    }
    __syncthreads();

    const int tx = tid & 15;          // col quad within the 64-col half
    const int ty = (tid >> 4) & 15;   // row groups: ty*4 and 64+ty*4
    const int h  = tid >> 8;          // column half 0/1

    float accf[8][4];
    #pragma unroll
    for (int i = 0; i < 8; ++i)
        #pragma unroll
        for (int j = 0; j < 4; ++j) accf[i][j] = 0.0f;

    #pragma unroll
    for (int kc = 0; kc < 4; ++kc) {        // 4 chunks of 32 k
        __half2 acc2[8][2];
        #pragma unroll
        for (int i = 0; i < 8; ++i) {
            acc2[i][0] = __floats2half2_rn(0.0f, 0.0f);
            acc2[i][1] = __floats2half2_rn(0.0f, 0.0f);
        }

        #pragma unroll
        for (int kk = 0; kk < 32; ++kk) {
            int k = kc * 32 + kk;
            uint4 xva = *(const uint4*)&sXd[k * 128 + ty * 4];
            uint4 xvb = *(const uint4*)&sXd[k * 128 + 64 + ty * 4];
            const __half2* pa = (const __half2*)&xva;
            const __half2* pb = (const __half2*)&xvb;

            uint2 wq = sWq[k * 32 + h * 16 + tx];
            __half2 wr0 = *(__half2*)&wq.x;
            __half2 wr1 = *(__half2*)&wq.y;

            #pragma unroll
            for (int i = 0; i < 4; ++i) {
                acc2[i][0] = __hfma2(pa[i], wr0, acc2[i][0]);
                acc2[i][1] = __hfma2(pa[i], wr1, acc2[i][1]);
                acc2[i + 4][0] = __hfma2(pb[i], wr0, acc2[i + 4][0]);
                acc2[i + 4][1] = __hfma2(pb[i], wr1, acc2[i + 4][1]);
            }
        }

        #pragma unroll
        for (int i = 0; i < 8; ++i) {
            float2 f0 = __half22float2(acc2[i][0]);
            float2 f1 = __half22float2(acc2[i][1]);
            accf[i][0] += f0.x; accf[i][1] += f0.y;
            accf[i][2] += f1.x; accf[i][3] += f1.y;
        }
    }

    // Epilogue: fp32 acc -> fp16 global
    const int col0 = h * 64 + tx * 4;
    #pragma unroll
    for (int i = 0; i < 8; ++i) {
        int r = (i < 4) ? (ty * 4 + i) : (64 + ty * 4 + i - 4);
        int grow = row0 + r;
        if (grow < N_TOT) {
            uint2 o;
            *(__half2*)&o.x = __floats2half2_rn(accf[i][0], accf[i][1]);
            *(__half2*)&o.y = __floats2half2_rn(accf[i][2], accf[i][3]);
            *(uint2*)&g_bufBh[(size_t)grow * HID + col0] = o;
        }
    }
}

// ---------------------------------------------------------------------------
// Aggregation: HALF-WARP per destination node (16 lanes x 8 channels).
// Frozen R10/R12 loop; activation via HW tanh (MUFU.TANH).
// out = act( bias + dinv*dinv * xw[self] + sum_j nrm[j] * xw[src[j]] )
// ---------------------------------------------------------------------------
__device__ __forceinline__ void fma8(float* a, const uint4& v, float n) {
    const __half2* p = (const __half2*)&v;
    float2 q0 = __half22float2(p[0]);
    float2 q1 = __half22float2(p[1]);
    float2 q2 = __half22float2(p[2]);
    float2 q3 = __half22float2(p[3]);
    a[0] += n * q0.x; a[1] += n * q0.y;
    a[2] += n * q1.x; a[3] += n * q1.y;
    a[4] += n * q2.x; a[5] += n * q2.y;
    a[6] += n * q3.x; a[7] += n * q3.y;
}

__global__ void __launch_bounds__(256)
agg_kernel(const float* __restrict__ bias, int act)
{
    int node = (blockIdx.x * blockDim.x + threadIdx.x) >> 4;  // half-warp id
    int ln   = threadIdx.x & 15;
    if (node >= N_TOT) return;

    const uint4* xw = (const uint4*)g_bufBh;

    int beg = g_off[node];
    int end = g_off[node + 1];

    float s = g_dinv[node];
    s = s * s;
    float4 b0 = ((const float4*)bias)[ln * 2];
    float4 b1 = ((const float4*)bias)[ln * 2 + 1];
    float a[8] = { b0.x, b0.y, b0.z, b0.w, b1.x, b1.y, b1.z, b1.w };

    uint4 self = xw[(size_t)node * 16 + ln];
    fma8(a, self, s);

    int j = beg;
    for (; j + 1 < end; j += 2) {
        int   s0 = g_srcs[j];
        int   s1 = g_srcs[j + 1];
        float n0 = g_nrm[j];
        float n1 = g_nrm[j + 1];
        uint4 v0 = xw[(size_t)s0 * 16 + ln];
        uint4 v1 = xw[(size_t)s1 * 16 + ln];
        fma8(a, v0, n0);
        fma8(a, v1, n1);
    }
    if (j < end) {
        int   s0 = g_srcs[j];
        float n0 = g_nrm[j];
        uint4 v0 = xw[(size_t)s0 * 16 + ln];
        fma8(a, v0, n0);
    }

    if (act) {
        #pragma unroll
        for (int i = 0; i < 8; ++i) a[i] = __tanhf(a[i]);
    }
    uint4 o;
    *(__half2*)&o.x = __floats2half2_rn(a[0], a[1]);
    *(__half2*)&o.y = __floats2half2_rn(a[2], a[3]);
    *(__half2*)&o.z = __floats2half2_rn(a[4], a[5]);
    *(__half2*)&o.w = __floats2half2_rn(a[6], a[7]);
    ((uint4*)g_bufAh)[(size_t)node * 16 + ln] = o;
}

// ---------------------------------------------------------------------------
// Global mean pool (batch sorted per tower). grid = 2 * POOL_BLOCKS_T.
// ---------------------------------------------------------------------------
#define POOL_CHUNK 128
#define POOL_BLOCKS_T ((N_NODES + POOL_CHUNK - 1) / POOL_CHUNK)

__global__ void pool_kernel(const int* __restrict__ batch1,
                            const int* __restrict__ batch2) {
    int tower = (blockIdx.x >= POOL_BLOCKS_T) ? 1 : 0;
    const int* batch = tower ? batch2 : batch1;
    int blk = blockIdx.x - tower * POOL_BLOCKS_T;
    int c  = threadIdx.x;
    int n0 = blk * POOL_CHUNK;
    int n1 = n0 + POOL_CHUNK;
    if (n1 > N_NODES) n1 = N_NODES;
    if (n0 >= N_NODES) return;

    int gbase = tower * G_GRAPHS;
    size_t nodeoff = (size_t)tower * N_NODES;

    float acc = 0.0f;
    int cur = batch[n0];
    int run = 0;
    for (int n = n0; n < n1; ++n) {
        int g = batch[n];
        if (g != cur) {
            atomicAdd(&g_pooled[(gbase + cur) * HID + c], acc);
            if (c == 0) atomicAdd(&g_cnt[gbase + cur], (float)run);
            acc = 0.0f; run = 0; cur = g;
        }
        acc += __half2float(g_bufAh[(nodeoff + n) * HID + c]);
        run++;
    }
    atomicAdd(&g_pooled[(gbase + cur) * HID + c], acc);
    if (c == 0) atomicAdd(&g_cnt[gbase + cur], (float)run);
}

// ---------------------------------------------------------------------------
// MLP head: fc1 (128->64, relu) + 5 x fc (64->64, relu). grid = 2 (towers).
// ---------------------------------------------------------------------------
__global__ void __launch_bounds__(512)
mlp_kernel(const float* __restrict__ fcW1, const float* __restrict__ fcb1,
           const float* __restrict__ fcW,  const float* __restrict__ fcb)
{
    __shared__ float ha[G_GRAPHS * OUT_DIM];
    __shared__ float hb[G_GRAPHS * OUT_DIM];
    int t = threadIdx.x;
    int tower = blockIdx.x;
    int gbase = tower * G_GRAPHS;

    for (int idx = t; idx < G_GRAPHS * OUT_DIM; idx += 512) {
        int g = idx >> 6, o = idx & 63;
        float ic = g_cnt[gbase + g];
        ic = 1.0f / fmaxf(ic, 1.0f);
        float s = fcb1[o];
        #pragma unroll 4
        for (int k = 0; k < HID; ++k)
            s += g_pooled[(gbase + g) * HID + k] * ic * fcW1[k * OUT_DIM + o];
        ha[idx] = fmaxf(s, 0.0f);
    }
    __syncthreads();

    float* srcb = ha;
    float* dstb = hb;
    for (int L = 0; L < 5; ++L) {
        const float* Wp = fcW + L * OUT_DIM * OUT_DIM;
        const float* bp = fcb + L * OUT_DIM;
        for (int idx = t; idx < G_GRAPHS * OUT_DIM; idx += 512) {
            int g = idx >> 6, o = idx & 63;
            float s = bp[o];
            #pragma unroll 8
            for (int k = 0; k < OUT_DIM; ++k)
                s += srcb[g * OUT_DIM + k] * Wp[k * OUT_DIM + o];
            dstb[idx] = fmaxf(s, 0.0f);
        }
        __syncthreads();
        float* tmp = srcb; srcb = dstb; dstb = tmp;
    }

    for (int idx = t; idx < G_GRAPHS * OUT_DIM; idx += 512)
        g_h[tower][idx] = srcb[idx];
}

__global__ void final_kernel(float* __restrict__ out) {
    int g = threadIdx.x;
    if (g < G_GRAPHS) {
        float s = 0.0f;
        #pragma unroll 8
        for (int k = 0; k < OUT_DIM; ++k) {
            float d = g_h[0][g * OUT_DIM + k] - g_h[1][g * OUT_DIM + k];
            s += d * d;
        }
        out[g] = sqrtf(s);
    }
}

// ---------------------------------------------------------------------------
// Host launcher
// ---------------------------------------------------------------------------
extern "C" void kernel_launch(void* const* d_in, const int* in_sizes, int n_in,
                              void* d_out, int out_size)
{
    const float* x1  = (const float*)d_in[0];
    const int*   ei1 = (const int*)  d_in[1];
    const float* ea1 = (const float*)d_in[2];
    const int*   bt1 = (const int*)  d_in[3];
    const float* x2  = (const float*)d_in[4];
    const int*   ei2 = (const int*)  d_in[5];
    const float* ea2 = (const float*)d_in[6];
    const int*   bt2 = (const int*)  d_in[7];
    const float* convW = (const float*)d_in[8];
    const float* convB = (const float*)d_in[9];
    const float* fcW1  = (const float*)d_in[10];
    const float* fcb1  = (const float*)d_in[11];
    const float* fcW   = (const float*)d_in[12];
    const float* fcb   = (const float*)d_in[13];

    const bool ACTS[6] = { true, true, false, true, true, true };

    cudaFuncSetAttribute(gemm_kernel,
                         cudaFuncAttributeMaxDynamicSharedMemorySize,
                         GEMM_SMEM_BYTES);

    const int NBN = (N_TOT + 255) / 256;
    const int NBE = (E_TOT + 255) / 256;
    const int GEMM_BLOCKS = (N_TOT + 127) / 128;
    const int AGG_BLOCKS = (N_TOT * 16) / 256;

    // Build unified dst-sorted CSR + norms (once; reused for 6 layers)
    zero_deg_kernel<<<NBN, 256>>>();
    deg_count_kernel<<<NBE, 256>>>(ei1, ea1, ei2, ea2);
    scan_block_kernel<<<N_SCAN_BLOCKS, SCAN_BLK>>>();
    scan_top_kernel<<<1, 256>>>();
    scan_add_kernel<<<NBN, 256>>>();
    scatter_kernel<<<NBE, 256>>>(ei1, ea1, ei2, ea2);

    // x -> fp16 (both towers) + pool accumulator zeroing
    conv_x_kernel<<<(N_TOT * 32 + 255) / 256, 256>>>(x1, x2);

    for (int L = 0; L < 6; ++L) {
        gemm_kernel<<<GEMM_BLOCKS, 512, GEMM_SMEM_BYTES>>>(
            convW + (size_t)L * HID * HID);
        agg_kernel<<<AGG_BLOCKS, 256>>>(convB + L * HID, ACTS[L] ? 1 : 0);
    }

    pool_kernel<<<2 * POOL_BLOCKS_T, 128>>>(bt1, bt2);
    mlp_kernel<<<2, 512>>>(fcW1, fcb1, fcW, fcb);

    final_kernel<<<1, 64>>>((float*)d_out);
}